// round 12
// baseline (speedup 1.0000x reference)
#include <cuda_runtime.h>
#include <cuda_bf16.h>

#define NN 100000
#define EE 400000
#define HC 128
#define NL 3
#define VV 100

typedef unsigned long long u64;
typedef unsigned int u32;
typedef unsigned short u16;

// ---------------- device scratch (static, no allocation) ----------------
__device__ float d_xt[NN * HC];                       // fp32 xt for gathers
__device__ __align__(16) u16 d_hh[NN * HC];           // activation bf16 hi
__device__ __align__(16) u16 d_hl[NN * HC];           // activation bf16 lo
__device__ __align__(16) u16 d_gh[NN * HC];           // dense1 out hi
__device__ __align__(16) u16 d_gl[NN * HC];           // dense1 out lo
__device__ __align__(16) u16 d_wimg[4 * 2 * 16384];   // W^T bf16 hi/lo images
__device__ float d_as[NN];
__device__ float d_ad[NN];
__device__ int   d_deg[NN];
__device__ int   d_rowptr[NN + 1];
__device__ int   d_fillp[NN];
__device__ int2  d_csr2[EE + NN];                     // packed (src, ea bits)
__device__ float d_easum[256];
__device__ float d_msum;
__device__ float d_ce[NL];

// ---------------- helpers ----------------
__device__ __forceinline__ float warp_sum(float v) {
#pragma unroll
    for (int o = 16; o; o >>= 1) v += __shfl_xor_sync(0xffffffffu, v, o);
    return v;
}
__device__ __forceinline__ u64 pk2(float lo, float hi) {
    u64 r;
    asm("mov.b64 %0, {%1, %2};" : "=l"(r)
        : "r"(__float_as_uint(lo)), "r"(__float_as_uint(hi)));
    return r;
}
__device__ __forceinline__ u64 pkdup(float a) {
    u64 r; u32 u = __float_as_uint(a);
    asm("mov.b64 %0, {%1, %1};" : "=l"(r) : "r"(u));
    return r;
}
__device__ __forceinline__ void unpk2(u64 v, float& lo, float& hi) {
    u32 a, b;
    asm("mov.b64 {%0, %1}, %2;" : "=r"(a), "=r"(b) : "l"(v));
    lo = __uint_as_float(a); hi = __uint_as_float(b);
}
#define FMA2(acc, a, b) asm("fma.rn.f32x2 %0, %1, %2, %0;" : "+l"(acc) : "l"(a), "l"(b))

__device__ __forceinline__ u32 pk_bf16(float lo, float hi) {
    u32 r;
    asm("cvt.rn.bf16x2.f32 %0, %1, %2;" : "=r"(r) : "f"(hi), "f"(lo));
    return r;
}
__device__ __forceinline__ float bf_res(float v) {
    __nv_bfloat16 h = __float2bfloat16(v);
    return v - __bfloat162float(h);
}

// bf16 mma.sync (standard PTX, works on plain sm_103 target)
#define MMA_BF16(c, a, b) \
    asm volatile("mma.sync.aligned.m16n8k16.row.col.f32.bf16.bf16.f32 " \
        "{%0,%1,%2,%3}, {%4,%5,%6,%7}, {%8,%9}, {%0,%1,%2,%3};" \
        : "+f"((c)[0]), "+f"((c)[1]), "+f"((c)[2]), "+f"((c)[3]) \
        : "r"((a)[0]), "r"((a)[1]), "r"((a)[2]), "r"((a)[3]), "r"((b)[0]), "r"((b)[1]))

// ---------------- setup: deg init + ea partial sums + d_ce + out init ----------------
// MUST be launched <<<256, 256>>>.
__global__ void k_setup(const float* __restrict__ ea, const float* __restrict__ eW,
                        const float* __restrict__ aE, const float* __restrict__ wpb,
                        float* __restrict__ out, int n, int e, int g) {
    int t = threadIdx.x;
    int i = blockIdx.x * 256 + t;
    const int stride = 256 * 256;
    if (i == 0) d_msum = 0.f;
    for (int j = i; j < n; j += stride) d_deg[j] = 1;        // self loop pre-counted
    for (int j = i; j < g; j += stride) out[j] = wpb[0];
    float s = 0.f;
    for (int j = i; j < e; j += stride) s += ea[j];
    s = warp_sum(s);
    __shared__ float sw[8];
    if ((t & 31) == 0) sw[t >> 5] = s;
    __syncthreads();
    if (t == 0) {
        float tot = 0.f;
#pragma unroll
        for (int k2 = 0; k2 < 8; ++k2) tot += sw[k2];
        d_easum[blockIdx.x] = tot;
    }
    // block 0, warps 0..2: ce[l] = dot(edge_W[l], att_edge[l])
    if (blockIdx.x == 0 && t < NL * 32) {
        int l = t >> 5, lane = t & 31;
        float v = 0.f;
#pragma unroll
        for (int q = 0; q < 4; ++q)
            v += eW[l * HC + lane * 4 + q] * aE[l * HC + lane * 4 + q];
        v = warp_sum(v);
        if (lane == 0) d_ce[l] = v;
    }
}

__global__ void k_count(const int* __restrict__ ei, int e) {
    int i = blockIdx.x * blockDim.x + threadIdx.x;
    if (i < e) atomicAdd(&d_deg[ei[e + i]], 1);
}

// single-block full scan of d_deg -> d_rowptr / d_fillp; also finalizes d_msum
__global__ void k_scanA(int n) {
    __shared__ int sh[1024];
    int t = threadIdx.x;
    if (t < 256) {
        float ms = d_easum[t];
        ms = warp_sum(ms);
        if ((t & 31) == 0) atomicAdd(&d_msum, ms);
    }
    int chunk = (n + 1023) >> 10;
    int lo = t * chunk;
    int hi = min(lo + chunk, n);
    int s = 0;
    for (int i = lo; i < hi; ++i) s += d_deg[i];
    sh[t] = s;
    __syncthreads();
#pragma unroll
    for (int off = 1; off < 1024; off <<= 1) {
        int u = (t >= off) ? sh[t - off] : 0;
        __syncthreads();
        sh[t] += u;
        __syncthreads();
    }
    int run = sh[t] - s;                    // exclusive prefix of this chunk
    for (int i = lo; i < hi; ++i) {
        run += d_deg[i];
        d_rowptr[i + 1] = run;
        if (i + 1 < n) d_fillp[i + 1] = run;
    }
    if (t == 0) { d_rowptr[0] = 0; d_fillp[0] = 0; }
}

__global__ void k_fill(const int* __restrict__ ei, const float* __restrict__ eattr,
                       int e, int n) {
    int i = blockIdx.x * blockDim.x + threadIdx.x;
    if (i >= e + n) return;
    int s, d;
    float ea;
    if (i < e) { s = ei[i]; d = ei[e + i]; ea = eattr[i]; }
    else { s = d = i - e; ea = d_msum * (1.0f / (float)e); }
    int p = atomicAdd(&d_fillp[d], 1);
    d_csr2[p] = make_int2(s, __float_as_int(ea));
}

// weight prep: W[k][n] (fp32) -> W^T[n][k] bf16 hi and lo, dense row-major
__global__ void k_wprep(const float* __restrict__ gatW, const float* __restrict__ linW) {
    const float* W = (blockIdx.x < 2) ? gatW + (blockIdx.x + 1) * HC * HC
                                      : linW + (blockIdx.x - 2) * HC * HC;
    u16* Gh = d_wimg + blockIdx.x * 32768;
    u16* Gl = Gh + 16384;
    for (int idx = threadIdx.x; idx < 16384; idx += 256) {
        int k = idx >> 7, nn = idx & 127;
        float v = W[idx];
        __nv_bfloat16 h = __float2bfloat16(v);
        float rv = v - __bfloat162float(h);
        __nv_bfloat16 lo = __float2bfloat16(rv);
        Gh[nn * HC + k] = __bfloat16_as_ushort(h);
        Gl[nn * HC + k] = __bfloat16_as_ushort(lo);
    }
}

// ---------------- FFMA GEMM (vocab GEMM only, 100 rows) ----------------
#define SMEM_GEMM ((HC * HC + 32 * HC) * 4)
__global__ void __launch_bounds__(256, 2)
k_gemm(const float* __restrict__ A, const float* __restrict__ W,
       float* __restrict__ C, const float* __restrict__ v1, const float* __restrict__ v2,
       int nrows) {
    extern __shared__ float smem[];
    float (*As)[HC] = (float(*)[HC])smem;
    float (*Ws)[HC] = (float(*)[HC])(smem + HC * HC);
    int t = threadIdx.x;
    int row0 = blockIdx.x * 128;
#pragma unroll
    for (int i = 0; i < 16; ++i) {
        int idx = t + i * 256;
        int r = idx >> 5, c = (idx & 31) * 4;
        float4 v = make_float4(0.f, 0.f, 0.f, 0.f);
        if (row0 + r < nrows) v = *(const float4*)&A[(row0 + r) * HC + c];
        *(float4*)&As[r][c] = v;
    }
    int tx = t & 15, ty = t >> 4;
    int cA = tx * 4, cB = 64 + tx * 4, r0 = ty * 8;
    u64 acc[8][4];
#pragma unroll
    for (int i = 0; i < 8; ++i)
#pragma unroll
        for (int j = 0; j < 4; ++j) acc[i][j] = 0ULL;
    for (int kt = 0; kt < 4; ++kt) {
        __syncthreads();
#pragma unroll
        for (int i = 0; i < 4; ++i) {
            int idx = t + i * 256;
            int r = idx >> 5, c = (idx & 31) * 4;
            *(float4*)&Ws[r][c] = *(const float4*)&W[(kt * 32 + r) * HC + c];
        }
        __syncthreads();
#pragma unroll 8
        for (int kk = 0; kk < 32; ++kk) {
            float4 wA = *(const float4*)&Ws[kk][cA];
            float4 wB = *(const float4*)&Ws[kk][cB];
            u64 w0 = pk2(wA.x, wA.y), w1 = pk2(wA.z, wA.w);
            u64 w2 = pk2(wB.x, wB.y), w3 = pk2(wB.z, wB.w);
            int k = kt * 32 + kk;
#pragma unroll
            for (int i = 0; i < 8; ++i) {
                u64 a2 = pkdup(As[r0 + i][k]);
                FMA2(acc[i][0], a2, w0); FMA2(acc[i][1], a2, w1);
                FMA2(acc[i][2], a2, w2); FMA2(acc[i][3], a2, w3);
            }
        }
    }
    float4 s1A = *(const float4*)&v1[cA], s1B = *(const float4*)&v1[cB];
    float4 s2A = *(const float4*)&v2[cA], s2B = *(const float4*)&v2[cB];
    float ps[8], pd[8];
#pragma unroll
    for (int i = 0; i < 8; ++i) {
        float4 oA, oB;
        unpk2(acc[i][0], oA.x, oA.y); unpk2(acc[i][1], oA.z, oA.w);
        unpk2(acc[i][2], oB.x, oB.y); unpk2(acc[i][3], oB.z, oB.w);
        ps[i] = oA.x * s1A.x + oA.y * s1A.y + oA.z * s1A.z + oA.w * s1A.w
              + oB.x * s1B.x + oB.y * s1B.y + oB.z * s1B.z + oB.w * s1B.w;
        pd[i] = oA.x * s2A.x + oA.y * s2A.y + oA.z * s2A.z + oA.w * s2A.w
              + oB.x * s2B.x + oB.y * s2B.y + oB.z * s2B.z + oB.w * s2B.w;
        int gr = row0 + r0 + i;
        if (gr < nrows) {
            *(float4*)&C[gr * HC + cA] = oA;
            *(float4*)&C[gr * HC + cB] = oB;
        }
    }
#pragma unroll
    for (int i = 0; i < 8; ++i) {
#pragma unroll
        for (int off = 1; off < 16; off <<= 1) {
            ps[i] += __shfl_xor_sync(0xffffffffu, ps[i], off);
            pd[i] += __shfl_xor_sync(0xffffffffu, pd[i], off);
        }
    }
    if (tx == 0) {
#pragma unroll
        for (int i = 0; i < 8; ++i) {
            int gr = row0 + r0 + i;
            if (gr < nrows) { d_as[gr] = ps[i]; d_ad[gr] = pd[i]; }
        }
    }
}

// ---------------- HMMA GEMM (mma.sync bf16, bf16x3 split) ----------------
#define ROWB 272
#define SA_H 0
#define SA_L 34816
#define SW_H 69632
#define SW_L 104448
#define SRED 139264
#define SMEM_HM (139264 + 1024)

__global__ void __launch_bounds__(256, 1)
k_hmma(const u16* __restrict__ Ah, const u16* __restrict__ Al,
       const u16* __restrict__ Wimg, const float* __restrict__ bias,
       float* __restrict__ C, const float* __restrict__ v1, const float* __restrict__ v2,
       const int* __restrict__ batch, float* __restrict__ gout,
       u16* __restrict__ Oh, u16* __restrict__ Ol, int nrows, int mode) {
    extern __shared__ char smc[];
    int t = threadIdx.x;
    int wid = t >> 5, lane = t & 31;
    int row0 = blockIdx.x * 128;
    int g = lane >> 2, tig = lane & 3;
    int warp_m = wid & 3, warp_n = wid >> 2;

    const uint4* A4h = (const uint4*)Ah;
    const uint4* A4l = (const uint4*)Al;
#pragma unroll
    for (int i = 0; i < 8; ++i) {
        int idx = t + i * 256;
        int r = idx >> 4, c8 = idx & 15;
        uint4 vh = make_uint4(0, 0, 0, 0), vl = vh;
        if (row0 + r < nrows) {
            vh = A4h[(row0 + r) * 16 + c8];
            vl = A4l[(row0 + r) * 16 + c8];
        }
        *(uint4*)(smc + SA_H + r * ROWB + c8 * 16) = vh;
        *(uint4*)(smc + SA_L + r * ROWB + c8 * 16) = vl;
    }
    const uint4* Wh4 = (const uint4*)Wimg;
    const uint4* Wl4 = (const uint4*)(Wimg + 16384);
#pragma unroll
    for (int i = 0; i < 8; ++i) {
        int idx = t + i * 256;
        int r = idx >> 4, c8 = idx & 15;
        *(uint4*)(smc + SW_H + r * ROWB + c8 * 16) = Wh4[idx];
        *(uint4*)(smc + SW_L + r * ROWB + c8 * 16) = Wl4[idx];
    }
    __syncthreads();

    float acc[2][8][4];
#pragma unroll
    for (int mt = 0; mt < 2; ++mt)
#pragma unroll
        for (int nt = 0; nt < 8; ++nt)
#pragma unroll
            for (int j = 0; j < 4; ++j) acc[mt][nt][j] = 0.f;

#pragma unroll
    for (int ks = 0; ks < 8; ++ks) {
        u32 ah[2][4], al[2][4];
#pragma unroll
        for (int mt = 0; mt < 2; ++mt) {
            int rb = (warp_m * 32 + mt * 16 + g) * ROWB + ks * 32 + tig * 4;
            int rb8 = rb + 8 * ROWB;
            ah[mt][0] = *(const u32*)(smc + SA_H + rb);
            ah[mt][1] = *(const u32*)(smc + SA_H + rb8);
            ah[mt][2] = *(const u32*)(smc + SA_H + rb + 16);
            ah[mt][3] = *(const u32*)(smc + SA_H + rb8 + 16);
            al[mt][0] = *(const u32*)(smc + SA_L + rb);
            al[mt][1] = *(const u32*)(smc + SA_L + rb8);
            al[mt][2] = *(const u32*)(smc + SA_L + rb + 16);
            al[mt][3] = *(const u32*)(smc + SA_L + rb8 + 16);
        }
#pragma unroll
        for (int nt = 0; nt < 8; ++nt) {
            int nb = (warp_n * 64 + nt * 8 + g) * ROWB + ks * 32 + tig * 4;
            u32 bh[2], bl[2];
            bh[0] = *(const u32*)(smc + SW_H + nb);
            bh[1] = *(const u32*)(smc + SW_H + nb + 16);
            bl[0] = *(const u32*)(smc + SW_L + nb);
            bl[1] = *(const u32*)(smc + SW_L + nb + 16);
#pragma unroll
            for (int mt = 0; mt < 2; ++mt) {
                MMA_BF16(acc[mt][nt], ah[mt], bh);
                MMA_BF16(acc[mt][nt], ah[mt], bl);
                MMA_BF16(acc[mt][nt], al[mt], bh);
            }
        }
    }
    __syncthreads();

    if (mode == 0) {
        float psA[2] = {0.f, 0.f}, psB[2] = {0.f, 0.f};
        float pdA[2] = {0.f, 0.f}, pdB[2] = {0.f, 0.f};
#pragma unroll
        for (int mt = 0; mt < 2; ++mt) {
            int lrA = warp_m * 32 + mt * 16 + g;
#pragma unroll
            for (int nt = 0; nt < 8; ++nt) {
                int col = warp_n * 64 + nt * 8 + tig * 2;
                float c0 = acc[mt][nt][0], c1 = acc[mt][nt][1];
                float c2 = acc[mt][nt][2], c3 = acc[mt][nt][3];
                float va = v1[col], vb = v1[col + 1];
                float wa = v2[col], wb = v2[col + 1];
                psA[mt] += c0 * va + c1 * vb;  pdA[mt] += c0 * wa + c1 * wb;
                psB[mt] += c2 * va + c3 * vb;  pdB[mt] += c2 * wa + c3 * wb;
                int grA = row0 + lrA;
                if (grA < nrows)
                    *(float2*)&C[grA * HC + col] = make_float2(c0, c1);
                if (grA + 8 < nrows)
                    *(float2*)&C[(grA + 8) * HC + col] = make_float2(c2, c3);
            }
        }
#pragma unroll
        for (int mt = 0; mt < 2; ++mt) {
#pragma unroll
            for (int off = 1; off < 4; off <<= 1) {
                psA[mt] += __shfl_xor_sync(0xffffffffu, psA[mt], off);
                psB[mt] += __shfl_xor_sync(0xffffffffu, psB[mt], off);
                pdA[mt] += __shfl_xor_sync(0xffffffffu, pdA[mt], off);
                pdB[mt] += __shfl_xor_sync(0xffffffffu, pdB[mt], off);
            }
        }
        float* sd = (float*)(smc + SRED);
        float* dd = sd + 128;
        if (warp_n == 1 && tig == 0) {
#pragma unroll
            for (int mt = 0; mt < 2; ++mt) {
                int lr = warp_m * 32 + mt * 16 + g;
                sd[lr] = psA[mt]; dd[lr] = pdA[mt];
                sd[lr + 8] = psB[mt]; dd[lr + 8] = pdB[mt];
            }
        }
        __syncthreads();
        if (warp_n == 0 && tig == 0) {
#pragma unroll
            for (int mt = 0; mt < 2; ++mt) {
                int lr = warp_m * 32 + mt * 16 + g;
                if (row0 + lr < nrows) {
                    d_as[row0 + lr] = psA[mt] + sd[lr];
                    d_ad[row0 + lr] = pdA[mt] + dd[lr];
                }
                if (row0 + lr + 8 < nrows) {
                    d_as[row0 + lr + 8] = psB[mt] + sd[lr + 8];
                    d_ad[row0 + lr + 8] = pdB[mt] + dd[lr + 8];
                }
            }
        }
    } else if (mode == 1) {
#pragma unroll
        for (int mt = 0; mt < 2; ++mt) {
            int lrA = warp_m * 32 + mt * 16 + g;
            int grA = row0 + lrA;
#pragma unroll
            for (int nt = 0; nt < 8; ++nt) {
                int col = warp_n * 64 + nt * 8 + tig * 2;
                float b0 = bias[col], b1 = bias[col + 1];
                float c0 = fmaxf(acc[mt][nt][0] + b0, 0.f);
                float c1 = fmaxf(acc[mt][nt][1] + b1, 0.f);
                float c2 = fmaxf(acc[mt][nt][2] + b0, 0.f);
                float c3 = fmaxf(acc[mt][nt][3] + b1, 0.f);
                if (grA < nrows) {
                    *(u32*)&Oh[grA * HC + col] = pk_bf16(c0, c1);
                    *(u32*)&Ol[grA * HC + col] = pk_bf16(bf_res(c0), bf_res(c1));
                }
                if (grA + 8 < nrows) {
                    *(u32*)&Oh[(grA + 8) * HC + col] = pk_bf16(c2, c3);
                    *(u32*)&Ol[(grA + 8) * HC + col] = pk_bf16(bf_res(c2), bf_res(c3));
                }
            }
        }
    } else {
        float psA[2] = {0.f, 0.f}, psB[2] = {0.f, 0.f};
#pragma unroll
        for (int mt = 0; mt < 2; ++mt) {
#pragma unroll
            for (int nt = 0; nt < 8; ++nt) {
                int col = warp_n * 64 + nt * 8 + tig * 2;
                float b0 = bias[col], b1 = bias[col + 1];
                float va = v1[col], vb = v1[col + 1];
                psA[mt] += fmaxf(acc[mt][nt][0] + b0, 0.f) * va
                         + fmaxf(acc[mt][nt][1] + b1, 0.f) * vb;
                psB[mt] += fmaxf(acc[mt][nt][2] + b0, 0.f) * va
                         + fmaxf(acc[mt][nt][3] + b1, 0.f) * vb;
            }
        }
#pragma unroll
        for (int mt = 0; mt < 2; ++mt) {
#pragma unroll
            for (int off = 1; off < 4; off <<= 1) {
                psA[mt] += __shfl_xor_sync(0xffffffffu, psA[mt], off);
                psB[mt] += __shfl_xor_sync(0xffffffffu, psB[mt], off);
            }
        }
        float* pp = (float*)(smc + SRED);
        if (warp_n == 1 && tig == 0) {
#pragma unroll
            for (int mt = 0; mt < 2; ++mt) {
                int lr = warp_m * 32 + mt * 16 + g;
                pp[lr] = psA[mt];
                pp[lr + 8] = psB[mt];
            }
        }
        __syncthreads();
        if (warp_n == 0 && tig == 0) {
#pragma unroll
            for (int mt = 0; mt < 2; ++mt) {
                int lr = warp_m * 32 + mt * 16 + g;
                if (row0 + lr < nrows)
                    atomicAdd(&gout[batch[row0 + lr]], psA[mt] + pp[lr]);
                if (row0 + lr + 8 < nrows)
                    atomicAdd(&gout[batch[row0 + lr + 8]], psB[mt] + pp[lr + 8]);
            }
        }
    }
}

// ---------------- fused GAT aggregate: shift-softmax + 8-wide gather groups ----------
__global__ void k_gat(const float* __restrict__ bias, const int* __restrict__ remap,
                      int l, int n) {
    int gw = (blockIdx.x * blockDim.x + threadIdx.x) >> 5;
    int lane = threadIdx.x & 31;
    if (gw >= n) return;
    float ce = d_ce[l];
    int beg = d_rowptr[gw], end = d_rowptr[gw + 1];
    int dmap = remap ? remap[gw] : gw;
    float adn = d_ad[dmap];

    float K = 0.f;
    float ssum = 0.f;
    float4 acc = make_float4(0.f, 0.f, 0.f, 0.f);

    for (int chunk = beg; chunk < end; chunk += 32) {
        int cnt = min(32, end - chunk);
        int sr = 0;
        float w = 0.f, lg = 0.f;
        if (lane < cnt) {
            int2 se = d_csr2[chunk + lane];
            float ea = __int_as_float(se.y);
            sr = remap ? remap[se.x] : se.x;
            float tt = d_as[sr] + adn + ce * ea;
            lg = tt > 0.f ? tt : 0.2f * tt;
        }
        if (chunk == beg) K = __shfl_sync(0xffffffffu, lg, 0);
        if (lane < cnt) w = __expf(lg - K);
        ssum += w;

        for (int c = 0; c < cnt; c += 8) {
            int ss[8]; float ww[8];
#pragma unroll
            for (int q = 0; q < 8; ++q) {
                ss[q] = __shfl_sync(0xffffffffu, sr, c + q);
                ww[q] = __shfl_sync(0xffffffffu, w, c + q);
            }
#pragma unroll
            for (int q = 0; q < 8; ++q) {
                if (ww[q] > 0.f) {
                    float4 v = *(const float4*)&d_xt[ss[q] * HC + lane * 4];
                    acc.x += ww[q] * v.x; acc.y += ww[q] * v.y;
                    acc.z += ww[q] * v.z; acc.w += ww[q] * v.w;
                }
            }
        }
    }

    ssum = warp_sum(ssum);
    float inv = 1.f / ssum;
    float4 b4 = *(const float4*)&bias[lane * 4];
    float4 o;
    o.x = acc.x * inv + b4.x; o.y = acc.y * inv + b4.y;
    o.z = acc.z * inv + b4.z; o.w = acc.w * inv + b4.w;
    float q = o.x * o.x + o.y * o.y + o.z * o.z + o.w * o.w;
    q = warp_sum(q);
    float sc2 = 1.f / fmaxf(sqrtf(q), 1e-12f);
    o.x *= sc2; o.y *= sc2; o.z *= sc2; o.w *= sc2;

    uint2 hw, lw;
    hw.x = pk_bf16(o.x, o.y); hw.y = pk_bf16(o.z, o.w);
    lw.x = pk_bf16(bf_res(o.x), bf_res(o.y));
    lw.y = pk_bf16(bf_res(o.z), bf_res(o.w));
    *(uint2*)&d_hh[gw * HC + lane * 4] = hw;
    *(uint2*)&d_hl[gw * HC + lane * 4] = lw;
}

// ---------------- launcher ----------------
extern "C" void kernel_launch(void* const* d_in, const int* in_sizes, int n_in,
                              void* d_out, int out_size) {
    const int*   x     = (const int*)d_in[0];
    const int*   ei    = (const int*)d_in[1];
    const float* eattr = (const float*)d_in[2];
    const int*   batch = (const int*)d_in[3];
    const float* emb   = (const float*)d_in[4];
    const float* gatW  = (const float*)d_in[5];
    const float* attS  = (const float*)d_in[6];
    const float* attD  = (const float*)d_in[7];
    const float* edgeW = (const float*)d_in[8];
    const float* attE  = (const float*)d_in[9];
    const float* gatB  = (const float*)d_in[10];
    const float* linW  = (const float*)d_in[11];
    const float* linB  = (const float*)d_in[12];
    const float* wpW   = (const float*)d_in[13];
    const float* wpB   = (const float*)d_in[14];
    float* out = (float*)d_out;

    int n = in_sizes[0];
    int e = in_sizes[1] / 2;
    int g = out_size;

    void* p;
    cudaGetSymbolAddress(&p, d_xt);  float* pxt = (float*)p;
    cudaGetSymbolAddress(&p, d_hh);  u16* phh = (u16*)p;
    cudaGetSymbolAddress(&p, d_hl);  u16* phl = (u16*)p;
    cudaGetSymbolAddress(&p, d_gh);  u16* pgh = (u16*)p;
    cudaGetSymbolAddress(&p, d_gl);  u16* pgl = (u16*)p;
    cudaGetSymbolAddress(&p, d_wimg); u16* pw = (u16*)p;

    cudaFuncSetAttribute(k_gemm, cudaFuncAttributeMaxDynamicSharedMemorySize, SMEM_GEMM);
    cudaFuncSetAttribute(k_hmma, cudaFuncAttributeMaxDynamicSharedMemorySize, SMEM_HM);

    int gblocks = (n + 127) / 128;
    int wblocks = (n + 7) / 8;

    // 1..4: setup + CSR build
    k_setup<<<256, 256>>>(eattr, edgeW, attE, wpB, out, n, e, g);
    k_count<<<(e + 255) / 256, 256>>>(ei, e);
    k_scanA<<<1, 1024>>>(n);
    k_fill<<<(e + n + 255) / 256, 256>>>(ei, eattr, e, n);

    // 5..6: layer 0 (vocab-factored) — heavy kernels land in the ncu window
    k_gemm<<<1, 256, SMEM_GEMM>>>(emb, gatW, pxt, attS, attD, VV);
    k_gat<<<wblocks, 256>>>(gatB, x, 0, n);

    // 7: weight images for HMMA layers
    k_wprep<<<4, 256>>>(gatW, linW);

    // 8..11: layers 1..2
    for (int l = 1; l < NL; ++l) {
        k_hmma<<<gblocks, 256, SMEM_HM>>>(phh, phl, pw + (l - 1) * 32768, (const float*)0,
                                          pxt, attS + l * HC, attD + l * HC,
                                          (const int*)0, (float*)0,
                                          (u16*)0, (u16*)0, n, 0);
        k_gat<<<wblocks, 256>>>(gatB + l * HC, (const int*)0, l, n);
    }

    // 12: dense layer 1
    k_hmma<<<gblocks, 256, SMEM_HM>>>(phh, phl, pw + 2 * 32768, linB,
                                      (float*)0, (const float*)0, (const float*)0,
                                      (const int*)0, (float*)0, pgh, pgl, n, 1);
    // 13: dense layer 2 + fused readout
    k_hmma<<<gblocks, 256, SMEM_HM>>>(pgh, pgl, pw + 3 * 32768, linB + HC,
                                      (float*)0, wpW, (const float*)0,
                                      batch, out, (u16*)0, (u16*)0, n, 2);
}

// round 14
// speedup vs baseline: 1.0632x; 1.0632x over previous
#include <cuda_runtime.h>
#include <cuda_bf16.h>

#define NN 100000
#define EE 400000
#define HC 128
#define NL 3
#define VV 100

typedef unsigned long long u64;
typedef unsigned int u32;
typedef unsigned short u16;

// ---------------- device scratch (static, no allocation) ----------------
__device__ float d_xt[NN * HC];                       // fp32 xt for gathers
__device__ __align__(16) u16 d_hh[NN * HC];           // activation bf16 hi
__device__ __align__(16) u16 d_hl[NN * HC];           // activation bf16 lo
__device__ __align__(16) u16 d_gh[NN * HC];           // dense1 out hi
__device__ __align__(16) u16 d_gl[NN * HC];           // dense1 out lo
__device__ __align__(16) u16 d_wimg[4 * 2 * 16384];   // W^T bf16 hi/lo images
__device__ float d_as[NN];
__device__ float d_ad[NN];
__device__ int   d_deg[NN];
__device__ int   d_incl[NN];
__device__ int   d_rowptr[NN + 1];
__device__ int   d_fillp[NN];
__device__ int2  d_csr2[EE + NN];                     // packed (src, ea bits)
__device__ int   d_bsum[128];
__device__ int   d_boff[128];
__device__ float d_easum[256];
__device__ float d_msum;
__device__ float d_ce[NL];

// ---------------- helpers ----------------
__device__ __forceinline__ float warp_sum(float v) {
#pragma unroll
    for (int o = 16; o; o >>= 1) v += __shfl_xor_sync(0xffffffffu, v, o);
    return v;
}
__device__ __forceinline__ u64 pk2(float lo, float hi) {
    u64 r;
    asm("mov.b64 %0, {%1, %2};" : "=l"(r)
        : "r"(__float_as_uint(lo)), "r"(__float_as_uint(hi)));
    return r;
}
__device__ __forceinline__ u64 pkdup(float a) {
    u64 r; u32 u = __float_as_uint(a);
    asm("mov.b64 %0, {%1, %1};" : "=l"(r) : "r"(u));
    return r;
}
__device__ __forceinline__ void unpk2(u64 v, float& lo, float& hi) {
    u32 a, b;
    asm("mov.b64 {%0, %1}, %2;" : "=r"(a), "=r"(b) : "l"(v));
    lo = __uint_as_float(a); hi = __uint_as_float(b);
}
#define FMA2(acc, a, b) asm("fma.rn.f32x2 %0, %1, %2, %0;" : "+l"(acc) : "l"(a), "l"(b))

__device__ __forceinline__ u32 pk_bf16(float lo, float hi) {
    u32 r;
    asm("cvt.rn.bf16x2.f32 %0, %1, %2;" : "=r"(r) : "f"(hi), "f"(lo));
    return r;
}
__device__ __forceinline__ float bf_res(float v) {
    __nv_bfloat16 h = __float2bfloat16(v);
    return v - __bfloat162float(h);
}

// bf16 mma.sync (standard PTX, works on plain sm_103 target)
#define MMA_BF16(c, a, b) \
    asm volatile("mma.sync.aligned.m16n8k16.row.col.f32.bf16.bf16.f32 " \
        "{%0,%1,%2,%3}, {%4,%5,%6,%7}, {%8,%9}, {%0,%1,%2,%3};" \
        : "+f"((c)[0]), "+f"((c)[1]), "+f"((c)[2]), "+f"((c)[3]) \
        : "r"((a)[0]), "r"((a)[1]), "r"((a)[2]), "r"((a)[3]), "r"((b)[0]), "r"((b)[1]))

// ---------------- setup: deg init + ea partial sums + d_ce + out init ----------------
// MUST be launched <<<256, 256>>>.
__global__ void k_setup(const float* __restrict__ ea, const float* __restrict__ eW,
                        const float* __restrict__ aE, const float* __restrict__ wpb,
                        float* __restrict__ out, int n, int e, int g) {
    int t = threadIdx.x;
    int i = blockIdx.x * 256 + t;
    const int stride = 256 * 256;
    for (int j = i; j < n; j += stride) d_deg[j] = 1;        // self loop pre-counted
    for (int j = i; j < g; j += stride) out[j] = wpb[0];
    float s = 0.f;
    for (int j = i; j < e; j += stride) s += ea[j];
    s = warp_sum(s);
    __shared__ float sw[8];
    if ((t & 31) == 0) sw[t >> 5] = s;
    __syncthreads();
    if (t == 0) {
        float tot = 0.f;
#pragma unroll
        for (int k2 = 0; k2 < 8; ++k2) tot += sw[k2];
        d_easum[blockIdx.x] = tot;
    }
    // block 0, warps 0..2: ce[l] = dot(edge_W[l], att_edge[l])
    if (blockIdx.x == 0 && t < NL * 32) {
        int l = t >> 5, lane = t & 31;
        float v = 0.f;
#pragma unroll
        for (int q = 0; q < 4; ++q)
            v += eW[l * HC + lane * 4 + q] * aE[l * HC + lane * 4 + q];
        v = warp_sum(v);
        if (lane == 0) d_ce[l] = v;
    }
}

__global__ void k_count(const int* __restrict__ ei, int e) {
    int i = blockIdx.x * blockDim.x + threadIdx.x;
    if (i < e) atomicAdd(&d_deg[ei[e + i]], 1);
}

__global__ void k_scan1(int n) {
    __shared__ int sh[1024];
    int t = threadIdx.x;
    int i = blockIdx.x * 1024 + t;
    int v = (i < n) ? d_deg[i] : 0;
    sh[t] = v;
    __syncthreads();
#pragma unroll
    for (int off = 1; off < 1024; off <<= 1) {
        int u = (t >= off) ? sh[t - off] : 0;
        __syncthreads();
        sh[t] += u;
        __syncthreads();
    }
    if (i < n) d_incl[i] = sh[t];
    if (t == 1023) d_bsum[blockIdx.x] = sh[1023];
}

// 256 threads, 1 block: block-offset scan + finalize d_msum
__global__ void k_scan2(int nb) {
    __shared__ int sh[256];
    __shared__ float fm[8];
    int t = threadIdx.x;
    // finalize msum from 256 partials
    float ms = d_easum[t];
    ms = warp_sum(ms);
    if ((t & 31) == 0) fm[t >> 5] = ms;
    int v = (t < nb) ? d_bsum[t] : 0;
    sh[t] = v;
    __syncthreads();
    if (t == 0) {
        float tot = 0.f;
#pragma unroll
        for (int k2 = 0; k2 < 8; ++k2) tot += fm[k2];
        d_msum = tot;
    }
#pragma unroll
    for (int off = 1; off < 256; off <<= 1) {
        int u = (t >= off) ? sh[t - off] : 0;
        __syncthreads();
        sh[t] += u;
        __syncthreads();
    }
    if (t < nb) d_boff[t] = sh[t] - v;
}

__global__ void k_scan3(int n) {
    int i = blockIdx.x * blockDim.x + threadIdx.x;
    if (i >= n) return;
    int v = d_incl[i] + d_boff[i >> 10];
    d_rowptr[i + 1] = v;
    if (i + 1 < n) d_fillp[i + 1] = v;
    if (i == 0) { d_rowptr[0] = 0; d_fillp[0] = 0; }
}

__global__ void k_fill(const int* __restrict__ ei, const float* __restrict__ eattr,
                       int e, int n) {
    int i = blockIdx.x * blockDim.x + threadIdx.x;
    if (i >= e + n) return;
    int s, d;
    float ea;
    if (i < e) { s = ei[i]; d = ei[e + i]; ea = eattr[i]; }
    else { s = d = i - e; ea = d_msum * (1.0f / (float)e); }
    int p = atomicAdd(&d_fillp[d], 1);
    d_csr2[p] = make_int2(s, __float_as_int(ea));
}

// weight prep: W[k][n] (fp32) -> W^T[n][k] bf16 hi and lo, dense row-major
__global__ void k_wprep(const float* __restrict__ gatW, const float* __restrict__ linW) {
    const float* W = (blockIdx.x < 2) ? gatW + (blockIdx.x + 1) * HC * HC
                                      : linW + (blockIdx.x - 2) * HC * HC;
    u16* Gh = d_wimg + blockIdx.x * 32768;
    u16* Gl = Gh + 16384;
    for (int idx = threadIdx.x; idx < 16384; idx += 256) {
        int k = idx >> 7, nn = idx & 127;
        float v = W[idx];
        __nv_bfloat16 h = __float2bfloat16(v);
        float rv = v - __bfloat162float(h);
        __nv_bfloat16 lo = __float2bfloat16(rv);
        Gh[nn * HC + k] = __bfloat16_as_ushort(h);
        Gl[nn * HC + k] = __bfloat16_as_ushort(lo);
    }
}

// ---------------- FFMA GEMM (vocab GEMM only, 100 rows) ----------------
#define SMEM_GEMM ((HC * HC + 32 * HC) * 4)
__global__ void __launch_bounds__(256, 2)
k_gemm(const float* __restrict__ A, const float* __restrict__ W,
       float* __restrict__ C, const float* __restrict__ v1, const float* __restrict__ v2,
       int nrows) {
    extern __shared__ float smem[];
    float (*As)[HC] = (float(*)[HC])smem;
    float (*Ws)[HC] = (float(*)[HC])(smem + HC * HC);
    int t = threadIdx.x;
    int row0 = blockIdx.x * 128;
#pragma unroll
    for (int i = 0; i < 16; ++i) {
        int idx = t + i * 256;
        int r = idx >> 5, c = (idx & 31) * 4;
        float4 v = make_float4(0.f, 0.f, 0.f, 0.f);
        if (row0 + r < nrows) v = *(const float4*)&A[(row0 + r) * HC + c];
        *(float4*)&As[r][c] = v;
    }
    int tx = t & 15, ty = t >> 4;
    int cA = tx * 4, cB = 64 + tx * 4, r0 = ty * 8;
    u64 acc[8][4];
#pragma unroll
    for (int i = 0; i < 8; ++i)
#pragma unroll
        for (int j = 0; j < 4; ++j) acc[i][j] = 0ULL;
    for (int kt = 0; kt < 4; ++kt) {
        __syncthreads();
#pragma unroll
        for (int i = 0; i < 4; ++i) {
            int idx = t + i * 256;
            int r = idx >> 5, c = (idx & 31) * 4;
            *(float4*)&Ws[r][c] = *(const float4*)&W[(kt * 32 + r) * HC + c];
        }
        __syncthreads();
#pragma unroll 8
        for (int kk = 0; kk < 32; ++kk) {
            float4 wA = *(const float4*)&Ws[kk][cA];
            float4 wB = *(const float4*)&Ws[kk][cB];
            u64 w0 = pk2(wA.x, wA.y), w1 = pk2(wA.z, wA.w);
            u64 w2 = pk2(wB.x, wB.y), w3 = pk2(wB.z, wB.w);
            int k = kt * 32 + kk;
#pragma unroll
            for (int i = 0; i < 8; ++i) {
                u64 a2 = pkdup(As[r0 + i][k]);
                FMA2(acc[i][0], a2, w0); FMA2(acc[i][1], a2, w1);
                FMA2(acc[i][2], a2, w2); FMA2(acc[i][3], a2, w3);
            }
        }
    }
    float4 s1A = *(const float4*)&v1[cA], s1B = *(const float4*)&v1[cB];
    float4 s2A = *(const float4*)&v2[cA], s2B = *(const float4*)&v2[cB];
    float ps[8], pd[8];
#pragma unroll
    for (int i = 0; i < 8; ++i) {
        float4 oA, oB;
        unpk2(acc[i][0], oA.x, oA.y); unpk2(acc[i][1], oA.z, oA.w);
        unpk2(acc[i][2], oB.x, oB.y); unpk2(acc[i][3], oB.z, oB.w);
        ps[i] = oA.x * s1A.x + oA.y * s1A.y + oA.z * s1A.z + oA.w * s1A.w
              + oB.x * s1B.x + oB.y * s1B.y + oB.z * s1B.z + oB.w * s1B.w;
        pd[i] = oA.x * s2A.x + oA.y * s2A.y + oA.z * s2A.z + oA.w * s2A.w
              + oB.x * s2B.x + oB.y * s2B.y + oB.z * s2B.z + oB.w * s2B.w;
        int gr = row0 + r0 + i;
        if (gr < nrows) {
            *(float4*)&C[gr * HC + cA] = oA;
            *(float4*)&C[gr * HC + cB] = oB;
        }
    }
#pragma unroll
    for (int i = 0; i < 8; ++i) {
#pragma unroll
        for (int off = 1; off < 16; off <<= 1) {
            ps[i] += __shfl_xor_sync(0xffffffffu, ps[i], off);
            pd[i] += __shfl_xor_sync(0xffffffffu, pd[i], off);
        }
    }
    if (tx == 0) {
#pragma unroll
        for (int i = 0; i < 8; ++i) {
            int gr = row0 + r0 + i;
            if (gr < nrows) { d_as[gr] = ps[i]; d_ad[gr] = pd[i]; }
        }
    }
}

// ---------------- HMMA GEMM (mma.sync bf16, bf16x3 split) ----------------
// A hi/lo staged in SMEM (272B-stride, conflict-free); W read directly from the
// 64KB L1-resident global image -> SMEM ~70KB -> 2 blocks/SM.
#define ROWB 272
#define SA_H 0
#define SA_L 34816
#define SRED 69632
#define SMEM_HM (69632 + 1024)

__global__ void __launch_bounds__(256, 2)
k_hmma(const u16* __restrict__ Ah, const u16* __restrict__ Al,
       const u16* __restrict__ Wimg, const float* __restrict__ bias,
       float* __restrict__ C, const float* __restrict__ v1, const float* __restrict__ v2,
       const int* __restrict__ batch, float* __restrict__ gout,
       u16* __restrict__ Oh, u16* __restrict__ Ol, int nrows, int mode) {
    extern __shared__ char smc[];
    int t = threadIdx.x;
    int wid = t >> 5, lane = t & 31;
    int row0 = blockIdx.x * 128;
    int g = lane >> 2, tig = lane & 3;
    int warp_m = wid & 3, warp_n = wid >> 2;

    const uint4* A4h = (const uint4*)Ah;
    const uint4* A4l = (const uint4*)Al;
#pragma unroll
    for (int i = 0; i < 8; ++i) {
        int idx = t + i * 256;
        int r = idx >> 4, c8 = idx & 15;
        uint4 vh = make_uint4(0, 0, 0, 0), vl = vh;
        if (row0 + r < nrows) {
            vh = A4h[(row0 + r) * 16 + c8];
            vl = A4l[(row0 + r) * 16 + c8];
        }
        *(uint4*)(smc + SA_H + r * ROWB + c8 * 16) = vh;
        *(uint4*)(smc + SA_L + r * ROWB + c8 * 16) = vl;
    }
    __syncthreads();

    const u16* Wh = Wimg;
    const u16* Wl = Wimg + 16384;

    float acc[2][8][4];
#pragma unroll
    for (int mt = 0; mt < 2; ++mt)
#pragma unroll
        for (int nt = 0; nt < 8; ++nt)
#pragma unroll
            for (int j = 0; j < 4; ++j) acc[mt][nt][j] = 0.f;

#pragma unroll
    for (int ks = 0; ks < 8; ++ks) {
        u32 ah[2][4], al[2][4];
#pragma unroll
        for (int mt = 0; mt < 2; ++mt) {
            int rb = (warp_m * 32 + mt * 16 + g) * ROWB + ks * 32 + tig * 4;
            int rb8 = rb + 8 * ROWB;
            ah[mt][0] = *(const u32*)(smc + SA_H + rb);
            ah[mt][1] = *(const u32*)(smc + SA_H + rb8);
            ah[mt][2] = *(const u32*)(smc + SA_H + rb + 16);
            ah[mt][3] = *(const u32*)(smc + SA_H + rb8 + 16);
            al[mt][0] = *(const u32*)(smc + SA_L + rb);
            al[mt][1] = *(const u32*)(smc + SA_L + rb8);
            al[mt][2] = *(const u32*)(smc + SA_L + rb + 16);
            al[mt][3] = *(const u32*)(smc + SA_L + rb8 + 16);
        }
        int kbase = ks * 16 + tig * 2;
#pragma unroll
        for (int nt = 0; nt < 8; ++nt) {
            int nn = warp_n * 64 + nt * 8 + g;
            u32 bh[2], bl[2];
            bh[0] = __ldg((const u32*)&Wh[nn * HC + kbase]);
            bh[1] = __ldg((const u32*)&Wh[nn * HC + kbase + 8]);
            bl[0] = __ldg((const u32*)&Wl[nn * HC + kbase]);
            bl[1] = __ldg((const u32*)&Wl[nn * HC + kbase + 8]);
#pragma unroll
            for (int mt = 0; mt < 2; ++mt) {
                MMA_BF16(acc[mt][nt], ah[mt], bh);
                MMA_BF16(acc[mt][nt], ah[mt], bl);
                MMA_BF16(acc[mt][nt], al[mt], bh);
            }
        }
    }
    __syncthreads();

    if (mode == 0) {
        float psA[2] = {0.f, 0.f}, psB[2] = {0.f, 0.f};
        float pdA[2] = {0.f, 0.f}, pdB[2] = {0.f, 0.f};
#pragma unroll
        for (int mt = 0; mt < 2; ++mt) {
            int lrA = warp_m * 32 + mt * 16 + g;
#pragma unroll
            for (int nt = 0; nt < 8; ++nt) {
                int col = warp_n * 64 + nt * 8 + tig * 2;
                float c0 = acc[mt][nt][0], c1 = acc[mt][nt][1];
                float c2 = acc[mt][nt][2], c3 = acc[mt][nt][3];
                float va = v1[col], vb = v1[col + 1];
                float wa = v2[col], wb = v2[col + 1];
                psA[mt] += c0 * va + c1 * vb;  pdA[mt] += c0 * wa + c1 * wb;
                psB[mt] += c2 * va + c3 * vb;  pdB[mt] += c2 * wa + c3 * wb;
                int grA = row0 + lrA;
                if (grA < nrows)
                    *(float2*)&C[grA * HC + col] = make_float2(c0, c1);
                if (grA + 8 < nrows)
                    *(float2*)&C[(grA + 8) * HC + col] = make_float2(c2, c3);
            }
        }
#pragma unroll
        for (int mt = 0; mt < 2; ++mt) {
#pragma unroll
            for (int off = 1; off < 4; off <<= 1) {
                psA[mt] += __shfl_xor_sync(0xffffffffu, psA[mt], off);
                psB[mt] += __shfl_xor_sync(0xffffffffu, psB[mt], off);
                pdA[mt] += __shfl_xor_sync(0xffffffffu, pdA[mt], off);
                pdB[mt] += __shfl_xor_sync(0xffffffffu, pdB[mt], off);
            }
        }
        float* sd = (float*)(smc + SRED);
        float* dd = sd + 128;
        if (warp_n == 1 && tig == 0) {
#pragma unroll
            for (int mt = 0; mt < 2; ++mt) {
                int lr = warp_m * 32 + mt * 16 + g;
                sd[lr] = psA[mt]; dd[lr] = pdA[mt];
                sd[lr + 8] = psB[mt]; dd[lr + 8] = pdB[mt];
            }
        }
        __syncthreads();
        if (warp_n == 0 && tig == 0) {
#pragma unroll
            for (int mt = 0; mt < 2; ++mt) {
                int lr = warp_m * 32 + mt * 16 + g;
                if (row0 + lr < nrows) {
                    d_as[row0 + lr] = psA[mt] + sd[lr];
                    d_ad[row0 + lr] = pdA[mt] + dd[lr];
                }
                if (row0 + lr + 8 < nrows) {
                    d_as[row0 + lr + 8] = psB[mt] + sd[lr + 8];
                    d_ad[row0 + lr + 8] = pdB[mt] + dd[lr + 8];
                }
            }
        }
    } else if (mode == 1) {
#pragma unroll
        for (int mt = 0; mt < 2; ++mt) {
            int lrA = warp_m * 32 + mt * 16 + g;
            int grA = row0 + lrA;
#pragma unroll
            for (int nt = 0; nt < 8; ++nt) {
                int col = warp_n * 64 + nt * 8 + tig * 2;
                float b0 = bias[col], b1 = bias[col + 1];
                float c0 = fmaxf(acc[mt][nt][0] + b0, 0.f);
                float c1 = fmaxf(acc[mt][nt][1] + b1, 0.f);
                float c2 = fmaxf(acc[mt][nt][2] + b0, 0.f);
                float c3 = fmaxf(acc[mt][nt][3] + b1, 0.f);
                if (grA < nrows) {
                    *(u32*)&Oh[grA * HC + col] = pk_bf16(c0, c1);
                    *(u32*)&Ol[grA * HC + col] = pk_bf16(bf_res(c0), bf_res(c1));
                }
                if (grA + 8 < nrows) {
                    *(u32*)&Oh[(grA + 8) * HC + col] = pk_bf16(c2, c3);
                    *(u32*)&Ol[(grA + 8) * HC + col] = pk_bf16(bf_res(c2), bf_res(c3));
                }
            }
        }
    } else {
        float psA[2] = {0.f, 0.f}, psB[2] = {0.f, 0.f};
#pragma unroll
        for (int mt = 0; mt < 2; ++mt) {
#pragma unroll
            for (int nt = 0; nt < 8; ++nt) {
                int col = warp_n * 64 + nt * 8 + tig * 2;
                float b0 = bias[col], b1 = bias[col + 1];
                float va = v1[col], vb = v1[col + 1];
                psA[mt] += fmaxf(acc[mt][nt][0] + b0, 0.f) * va
                         + fmaxf(acc[mt][nt][1] + b1, 0.f) * vb;
                psB[mt] += fmaxf(acc[mt][nt][2] + b0, 0.f) * va
                         + fmaxf(acc[mt][nt][3] + b1, 0.f) * vb;
            }
        }
#pragma unroll
        for (int mt = 0; mt < 2; ++mt) {
#pragma unroll
            for (int off = 1; off < 4; off <<= 1) {
                psA[mt] += __shfl_xor_sync(0xffffffffu, psA[mt], off);
                psB[mt] += __shfl_xor_sync(0xffffffffu, psB[mt], off);
            }
        }
        float* pp = (float*)(smc + SRED);
        if (warp_n == 1 && tig == 0) {
#pragma unroll
            for (int mt = 0; mt < 2; ++mt) {
                int lr = warp_m * 32 + mt * 16 + g;
                pp[lr] = psA[mt];
                pp[lr + 8] = psB[mt];
            }
        }
        __syncthreads();
        if (warp_n == 0 && tig == 0) {
#pragma unroll
            for (int mt = 0; mt < 2; ++mt) {
                int lr = warp_m * 32 + mt * 16 + g;
                if (row0 + lr < nrows)
                    atomicAdd(&gout[batch[row0 + lr]], psA[mt] + pp[lr]);
                if (row0 + lr + 8 < nrows)
                    atomicAdd(&gout[batch[row0 + lr + 8]], psB[mt] + pp[lr + 8]);
            }
        }
    }
}

// ---------------- fused GAT aggregate: shift-softmax + 8-wide gather groups ----------
__global__ void k_gat(const float* __restrict__ bias, const int* __restrict__ remap,
                      int l, int n) {
    int gw = (blockIdx.x * blockDim.x + threadIdx.x) >> 5;
    int lane = threadIdx.x & 31;
    if (gw >= n) return;
    float ce = d_ce[l];
    int beg = d_rowptr[gw], end = d_rowptr[gw + 1];
    int dmap = remap ? remap[gw] : gw;
    float adn = d_ad[dmap];

    float K = 0.f;
    float ssum = 0.f;
    float4 acc = make_float4(0.f, 0.f, 0.f, 0.f);

    for (int chunk = beg; chunk < end; chunk += 32) {
        int cnt = min(32, end - chunk);
        int sr = 0;
        float w = 0.f, lg = 0.f;
        if (lane < cnt) {
            int2 se = d_csr2[chunk + lane];
            float ea = __int_as_float(se.y);
            sr = remap ? remap[se.x] : se.x;
            float tt = d_as[sr] + adn + ce * ea;
            lg = tt > 0.f ? tt : 0.2f * tt;
        }
        if (chunk == beg) K = __shfl_sync(0xffffffffu, lg, 0);
        if (lane < cnt) w = __expf(lg - K);
        ssum += w;

        for (int c = 0; c < cnt; c += 8) {
            int ss[8]; float ww[8];
#pragma unroll
            for (int q = 0; q < 8; ++q) {
                ss[q] = __shfl_sync(0xffffffffu, sr, c + q);
                ww[q] = __shfl_sync(0xffffffffu, w, c + q);
            }
#pragma unroll
            for (int q = 0; q < 8; ++q) {
                if (ww[q] > 0.f) {
                    float4 v = *(const float4*)&d_xt[ss[q] * HC + lane * 4];
                    acc.x += ww[q] * v.x; acc.y += ww[q] * v.y;
                    acc.z += ww[q] * v.z; acc.w += ww[q] * v.w;
                }
            }
        }
    }

    ssum = warp_sum(ssum);
    float inv = 1.f / ssum;
    float4 b4 = *(const float4*)&bias[lane * 4];
    float4 o;
    o.x = acc.x * inv + b4.x; o.y = acc.y * inv + b4.y;
    o.z = acc.z * inv + b4.z; o.w = acc.w * inv + b4.w;
    float q = o.x * o.x + o.y * o.y + o.z * o.z + o.w * o.w;
    q = warp_sum(q);
    float sc2 = 1.f / fmaxf(sqrtf(q), 1e-12f);
    o.x *= sc2; o.y *= sc2; o.z *= sc2; o.w *= sc2;

    uint2 hw, lw;
    hw.x = pk_bf16(o.x, o.y); hw.y = pk_bf16(o.z, o.w);
    lw.x = pk_bf16(bf_res(o.x), bf_res(o.y));
    lw.y = pk_bf16(bf_res(o.z), bf_res(o.w));
    *(uint2*)&d_hh[gw * HC + lane * 4] = hw;
    *(uint2*)&d_hl[gw * HC + lane * 4] = lw;
}

// ---------------- launcher ----------------
extern "C" void kernel_launch(void* const* d_in, const int* in_sizes, int n_in,
                              void* d_out, int out_size) {
    const int*   x     = (const int*)d_in[0];
    const int*   ei    = (const int*)d_in[1];
    const float* eattr = (const float*)d_in[2];
    const int*   batch = (const int*)d_in[3];
    const float* emb   = (const float*)d_in[4];
    const float* gatW  = (const float*)d_in[5];
    const float* attS  = (const float*)d_in[6];
    const float* attD  = (const float*)d_in[7];
    const float* edgeW = (const float*)d_in[8];
    const float* attE  = (const float*)d_in[9];
    const float* gatB  = (const float*)d_in[10];
    const float* linW  = (const float*)d_in[11];
    const float* linB  = (const float*)d_in[12];
    const float* wpW   = (const float*)d_in[13];
    const float* wpB   = (const float*)d_in[14];
    float* out = (float*)d_out;

    int n = in_sizes[0];
    int e = in_sizes[1] / 2;
    int g = out_size;

    void* p;
    cudaGetSymbolAddress(&p, d_xt);  float* pxt = (float*)p;
    cudaGetSymbolAddress(&p, d_hh);  u16* phh = (u16*)p;
    cudaGetSymbolAddress(&p, d_hl);  u16* phl = (u16*)p;
    cudaGetSymbolAddress(&p, d_gh);  u16* pgh = (u16*)p;
    cudaGetSymbolAddress(&p, d_gl);  u16* pgl = (u16*)p;
    cudaGetSymbolAddress(&p, d_wimg); u16* pw = (u16*)p;

    cudaFuncSetAttribute(k_gemm, cudaFuncAttributeMaxDynamicSharedMemorySize, SMEM_GEMM);
    cudaFuncSetAttribute(k_hmma, cudaFuncAttributeMaxDynamicSharedMemorySize, SMEM_HM);

    int gblocks = (n + 127) / 128;
    int wblocks = (n + 7) / 8;
    int nb = (n + 1023) / 1024;

    // 1..3: setup + count + scan stage 1
    k_setup<<<256, 256>>>(eattr, edgeW, attE, wpB, out, n, e, g);
    k_count<<<(e + 255) / 256, 256>>>(ei, e);
    k_scan1<<<nb, 1024>>>(n);
    // 4: vocab GEMM (independent of CSR) — lands in the ncu capture window
    k_gemm<<<1, 256, SMEM_GEMM>>>(emb, gatW, pxt, attS, attD, VV);
    // 5..7: scan finish + CSR fill
    k_scan2<<<1, 256>>>(nb);
    k_scan3<<<(n + 255) / 256, 256>>>(n);
    k_fill<<<(e + n + 255) / 256, 256>>>(ei, eattr, e, n);
    // 8: weight images
    k_wprep<<<4, 256>>>(gatW, linW);

    // 9: layer-0 GAT aggregate (vocab-factored)
    k_gat<<<wblocks, 256>>>(gatB, x, 0, n);

    // 10..13: layers 1..2
    for (int l = 1; l < NL; ++l) {
        k_hmma<<<gblocks, 256, SMEM_HM>>>(phh, phl, pw + (l - 1) * 32768, (const float*)0,
                                          pxt, attS + l * HC, attD + l * HC,
                                          (const int*)0, (float*)0,
                                          (u16*)0, (u16*)0, n, 0);
        k_gat<<<wblocks, 256>>>(gatB + l * HC, (const int*)0, l, n);
    }

    // 14: dense layer 1
    k_hmma<<<gblocks, 256, SMEM_HM>>>(phh, phl, pw + 2 * 32768, linB,
                                      (float*)0, (const float*)0, (const float*)0,
                                      (const int*)0, (float*)0, pgh, pgl, n, 1);
    // 15: dense layer 2 + fused readout
    k_hmma<<<gblocks, 256, SMEM_HM>>>(pgh, pgl, pw + 3 * 32768, linB + HC,
                                      (float*)0, wpW, (const float*)0,
                                      batch, out, (u16*)0, (u16*)0, n, 2);
}

// round 15
// speedup vs baseline: 1.3855x; 1.3031x over previous
#include <cuda_runtime.h>
#include <cuda_bf16.h>

#define NN 100000
#define EE 400000
#define HC 128
#define NL 3
#define VV 100

typedef unsigned long long u64;
typedef unsigned int u32;
typedef unsigned short u16;

// ---------------- device scratch (static, no allocation) ----------------
__device__ float d_xt[NN * HC];                       // fp32 xt for gathers
__device__ __align__(16) u16 d_hh[NN * HC];           // activation bf16 hi
__device__ __align__(16) u16 d_hl[NN * HC];           // activation bf16 lo
__device__ __align__(16) u16 d_gh[NN * HC];           // dense1 out hi
__device__ __align__(16) u16 d_gl[NN * HC];           // dense1 out lo
__device__ __align__(16) u16 d_wimg[4 * 2 * 16384];   // W^T bf16 hi/lo images
__device__ float d_as[NN];
__device__ float d_ad[NN];
__device__ int   d_deg[NN];
__device__ int   d_incl[NN];
__device__ int   d_rowptr[NN + 1];
__device__ int   d_fillp[NN];
__device__ int2  d_csr2[EE + NN];                     // packed (src, ea bits)
__device__ int   d_bsum[128];
__device__ int   d_boff[128];
__device__ float d_easum[256];
__device__ float d_msum;
__device__ float d_ce[NL];

// ---------------- helpers ----------------
__device__ __forceinline__ float warp_sum(float v) {
#pragma unroll
    for (int o = 16; o; o >>= 1) v += __shfl_xor_sync(0xffffffffu, v, o);
    return v;
}
__device__ __forceinline__ u32 pk_bf16(float lo, float hi) {
    u32 r;
    asm("cvt.rn.bf16x2.f32 %0, %1, %2;" : "=r"(r) : "f"(hi), "f"(lo));
    return r;
}
__device__ __forceinline__ float bf_res(float v) {
    __nv_bfloat16 h = __float2bfloat16(v);
    return v - __bfloat162float(h);
}

// bf16 mma.sync (standard PTX, works on plain sm_103 target)
#define MMA_BF16(c, a, b) \
    asm volatile("mma.sync.aligned.m16n8k16.row.col.f32.bf16.bf16.f32 " \
        "{%0,%1,%2,%3}, {%4,%5,%6,%7}, {%8,%9}, {%0,%1,%2,%3};" \
        : "+f"((c)[0]), "+f"((c)[1]), "+f"((c)[2]), "+f"((c)[3]) \
        : "r"((a)[0]), "r"((a)[1]), "r"((a)[2]), "r"((a)[3]), "r"((b)[0]), "r"((b)[1]))

// ---------------- setup: deg init + ea partial sums + d_ce + out init ----------------
// MUST be launched <<<256, 256>>>.
__global__ void k_setup(const float* __restrict__ ea, const float* __restrict__ eW,
                        const float* __restrict__ aE, const float* __restrict__ wpb,
                        float* __restrict__ out, int n, int e, int g) {
    int t = threadIdx.x;
    int i = blockIdx.x * 256 + t;
    const int stride = 256 * 256;
    for (int j = i; j < n; j += stride) d_deg[j] = 1;        // self loop pre-counted
    for (int j = i; j < g; j += stride) out[j] = wpb[0];
    float s = 0.f;
    for (int j = i; j < e; j += stride) s += ea[j];
    s = warp_sum(s);
    __shared__ float sw[8];
    if ((t & 31) == 0) sw[t >> 5] = s;
    __syncthreads();
    if (t == 0) {
        float tot = 0.f;
#pragma unroll
        for (int k2 = 0; k2 < 8; ++k2) tot += sw[k2];
        d_easum[blockIdx.x] = tot;
    }
    // block 0, warps 0..2: ce[l] = dot(edge_W[l], att_edge[l])
    if (blockIdx.x == 0 && t < NL * 32) {
        int l = t >> 5, lane = t & 31;
        float v = 0.f;
#pragma unroll
        for (int q = 0; q < 4; ++q)
            v += eW[l * HC + lane * 4 + q] * aE[l * HC + lane * 4 + q];
        v = warp_sum(v);
        if (lane == 0) d_ce[l] = v;
    }
}

__global__ void k_count(const int* __restrict__ ei, int e) {
    int i = blockIdx.x * blockDim.x + threadIdx.x;
    if (i < e) atomicAdd(&d_deg[ei[e + i]], 1);
}

__global__ void k_scan1(int n) {
    __shared__ int sh[1024];
    int t = threadIdx.x;
    int i = blockIdx.x * 1024 + t;
    int v = (i < n) ? d_deg[i] : 0;
    sh[t] = v;
    __syncthreads();
#pragma unroll
    for (int off = 1; off < 1024; off <<= 1) {
        int u = (t >= off) ? sh[t - off] : 0;
        __syncthreads();
        sh[t] += u;
        __syncthreads();
    }
    if (i < n) d_incl[i] = sh[t];
    if (t == 1023) d_bsum[blockIdx.x] = sh[1023];
}

// 256 threads, 1 block: block-offset scan + finalize d_msum
__global__ void k_scan2(int nb) {
    __shared__ int sh[256];
    __shared__ float fm[8];
    int t = threadIdx.x;
    float ms = d_easum[t];
    ms = warp_sum(ms);
    if ((t & 31) == 0) fm[t >> 5] = ms;
    int v = (t < nb) ? d_bsum[t] : 0;
    sh[t] = v;
    __syncthreads();
    if (t == 0) {
        float tot = 0.f;
#pragma unroll
        for (int k2 = 0; k2 < 8; ++k2) tot += fm[k2];
        d_msum = tot;
    }
#pragma unroll
    for (int off = 1; off < 256; off <<= 1) {
        int u = (t >= off) ? sh[t - off] : 0;
        __syncthreads();
        sh[t] += u;
        __syncthreads();
    }
    if (t < nb) d_boff[t] = sh[t] - v;
}

__global__ void k_scan3(int n) {
    int i = blockIdx.x * blockDim.x + threadIdx.x;
    if (i >= n) return;
    int v = d_incl[i] + d_boff[i >> 10];
    d_rowptr[i + 1] = v;
    if (i + 1 < n) d_fillp[i + 1] = v;
    if (i == 0) { d_rowptr[0] = 0; d_fillp[0] = 0; }
}

__global__ void k_fill(const int* __restrict__ ei, const float* __restrict__ eattr,
                       int e, int n) {
    int i = blockIdx.x * blockDim.x + threadIdx.x;
    if (i >= e + n) return;
    int s, d;
    float ea;
    if (i < e) { s = ei[i]; d = ei[e + i]; ea = eattr[i]; }
    else { s = d = i - e; ea = d_msum * (1.0f / (float)e); }
    int p = atomicAdd(&d_fillp[d], 1);
    d_csr2[p] = make_int2(s, __float_as_int(ea));
}

// weight prep: W[k][n] (fp32) -> W^T[n][k] bf16 hi and lo, dense row-major
__global__ void k_wprep(const float* __restrict__ gatW, const float* __restrict__ linW) {
    const float* W = (blockIdx.x < 2) ? gatW + (blockIdx.x + 1) * HC * HC
                                      : linW + (blockIdx.x - 2) * HC * HC;
    u16* Gh = d_wimg + blockIdx.x * 32768;
    u16* Gl = Gh + 16384;
    for (int idx = threadIdx.x; idx < 16384; idx += 256) {
        int k = idx >> 7, nn = idx & 127;
        float v = W[idx];
        __nv_bfloat16 h = __float2bfloat16(v);
        float rv = v - __bfloat162float(h);
        __nv_bfloat16 lo = __float2bfloat16(rv);
        Gh[nn * HC + k] = __bfloat16_as_ushort(h);
        Gl[nn * HC + k] = __bfloat16_as_ushort(lo);
    }
}

// ---------------- vocab GEMM: one block per emb row (100 blocks, parallel) --------
// xtV[r][c] = sum_k emb[r][k] * W[k][c];  fused a_s/a_d dots.
__global__ void __launch_bounds__(128, 8)
k_vgemm(const float* __restrict__ emb, const float* __restrict__ W,
        const float* __restrict__ v1, const float* __restrict__ v2) {
    int r = blockIdx.x, c = threadIdx.x;
    __shared__ float row[HC];
    __shared__ float s1[4], s2[4];
    row[c] = emb[r * HC + c];
    __syncthreads();
    float acc = 0.f;
#pragma unroll
    for (int k = 0; k < HC; ++k)
        acc = fmaf(row[k], W[k * HC + c], acc);
    d_xt[r * HC + c] = acc;
    float ps = acc * v1[c], pd = acc * v2[c];
    ps = warp_sum(ps); pd = warp_sum(pd);
    if ((c & 31) == 0) { s1[c >> 5] = ps; s2[c >> 5] = pd; }
    __syncthreads();
    if (c == 0) d_as[r] = s1[0] + s1[1] + s1[2] + s1[3];
    if (c == 1) d_ad[r] = s2[0] + s2[1] + s2[2] + s2[3];
}

// ---------------- HMMA GEMM (mma.sync bf16, bf16x3 split) ----------------
// Validated R10 config: A and W both staged in SMEM at 272B row stride.
#define ROWB 272
#define SA_H 0
#define SA_L 34816
#define SW_H 69632
#define SW_L 104448
#define SRED 139264
#define SMEM_HM (139264 + 1024)

__global__ void __launch_bounds__(256, 1)
k_hmma(const u16* __restrict__ Ah, const u16* __restrict__ Al,
       const u16* __restrict__ Wimg, const float* __restrict__ bias,
       float* __restrict__ C, const float* __restrict__ v1, const float* __restrict__ v2,
       const int* __restrict__ batch, float* __restrict__ gout,
       u16* __restrict__ Oh, u16* __restrict__ Ol, int nrows, int mode) {
    extern __shared__ char smc[];
    int t = threadIdx.x;
    int wid = t >> 5, lane = t & 31;
    int row0 = blockIdx.x * 128;
    int g = lane >> 2, tig = lane & 3;
    int warp_m = wid & 3, warp_n = wid >> 2;

    const uint4* A4h = (const uint4*)Ah;
    const uint4* A4l = (const uint4*)Al;
#pragma unroll
    for (int i = 0; i < 8; ++i) {
        int idx = t + i * 256;
        int r = idx >> 4, c8 = idx & 15;
        uint4 vh = make_uint4(0, 0, 0, 0), vl = vh;
        if (row0 + r < nrows) {
            vh = A4h[(row0 + r) * 16 + c8];
            vl = A4l[(row0 + r) * 16 + c8];
        }
        *(uint4*)(smc + SA_H + r * ROWB + c8 * 16) = vh;
        *(uint4*)(smc + SA_L + r * ROWB + c8 * 16) = vl;
    }
    const uint4* Wh4 = (const uint4*)Wimg;
    const uint4* Wl4 = (const uint4*)(Wimg + 16384);
#pragma unroll
    for (int i = 0; i < 8; ++i) {
        int idx = t + i * 256;
        int r = idx >> 4, c8 = idx & 15;
        *(uint4*)(smc + SW_H + r * ROWB + c8 * 16) = Wh4[idx];
        *(uint4*)(smc + SW_L + r * ROWB + c8 * 16) = Wl4[idx];
    }
    __syncthreads();

    float acc[2][8][4];
#pragma unroll
    for (int mt = 0; mt < 2; ++mt)
#pragma unroll
        for (int nt = 0; nt < 8; ++nt)
#pragma unroll
            for (int j = 0; j < 4; ++j) acc[mt][nt][j] = 0.f;

#pragma unroll
    for (int ks = 0; ks < 8; ++ks) {
        u32 ah[2][4], al[2][4];
#pragma unroll
        for (int mt = 0; mt < 2; ++mt) {
            int rb = (warp_m * 32 + mt * 16 + g) * ROWB + ks * 32 + tig * 4;
            int rb8 = rb + 8 * ROWB;
            ah[mt][0] = *(const u32*)(smc + SA_H + rb);
            ah[mt][1] = *(const u32*)(smc + SA_H + rb8);
            ah[mt][2] = *(const u32*)(smc + SA_H + rb + 16);
            ah[mt][3] = *(const u32*)(smc + SA_H + rb8 + 16);
            al[mt][0] = *(const u32*)(smc + SA_L + rb);
            al[mt][1] = *(const u32*)(smc + SA_L + rb8);
            al[mt][2] = *(const u32*)(smc + SA_L + rb + 16);
            al[mt][3] = *(const u32*)(smc + SA_L + rb8 + 16);
        }
#pragma unroll
        for (int nt = 0; nt < 8; ++nt) {
            int nb = (warp_n * 64 + nt * 8 + g) * ROWB + ks * 32 + tig * 4;
            u32 bh[2], bl[2];
            bh[0] = *(const u32*)(smc + SW_H + nb);
            bh[1] = *(const u32*)(smc + SW_H + nb + 16);
            bl[0] = *(const u32*)(smc + SW_L + nb);
            bl[1] = *(const u32*)(smc + SW_L + nb + 16);
#pragma unroll
            for (int mt = 0; mt < 2; ++mt) {
                MMA_BF16(acc[mt][nt], ah[mt], bh);
                MMA_BF16(acc[mt][nt], ah[mt], bl);
                MMA_BF16(acc[mt][nt], al[mt], bh);
            }
        }
    }
    __syncthreads();

    if (mode == 0) {
        float psA[2] = {0.f, 0.f}, psB[2] = {0.f, 0.f};
        float pdA[2] = {0.f, 0.f}, pdB[2] = {0.f, 0.f};
#pragma unroll
        for (int mt = 0; mt < 2; ++mt) {
            int lrA = warp_m * 32 + mt * 16 + g;
#pragma unroll
            for (int nt = 0; nt < 8; ++nt) {
                int col = warp_n * 64 + nt * 8 + tig * 2;
                float c0 = acc[mt][nt][0], c1 = acc[mt][nt][1];
                float c2 = acc[mt][nt][2], c3 = acc[mt][nt][3];
                float va = v1[col], vb = v1[col + 1];
                float wa = v2[col], wb = v2[col + 1];
                psA[mt] += c0 * va + c1 * vb;  pdA[mt] += c0 * wa + c1 * wb;
                psB[mt] += c2 * va + c3 * vb;  pdB[mt] += c2 * wa + c3 * wb;
                int grA = row0 + lrA;
                if (grA < nrows)
                    *(float2*)&C[grA * HC + col] = make_float2(c0, c1);
                if (grA + 8 < nrows)
                    *(float2*)&C[(grA + 8) * HC + col] = make_float2(c2, c3);
            }
        }
#pragma unroll
        for (int mt = 0; mt < 2; ++mt) {
#pragma unroll
            for (int off = 1; off < 4; off <<= 1) {
                psA[mt] += __shfl_xor_sync(0xffffffffu, psA[mt], off);
                psB[mt] += __shfl_xor_sync(0xffffffffu, psB[mt], off);
                pdA[mt] += __shfl_xor_sync(0xffffffffu, pdA[mt], off);
                pdB[mt] += __shfl_xor_sync(0xffffffffu, pdB[mt], off);
            }
        }
        float* sd = (float*)(smc + SRED);
        float* dd = sd + 128;
        if (warp_n == 1 && tig == 0) {
#pragma unroll
            for (int mt = 0; mt < 2; ++mt) {
                int lr = warp_m * 32 + mt * 16 + g;
                sd[lr] = psA[mt]; dd[lr] = pdA[mt];
                sd[lr + 8] = psB[mt]; dd[lr + 8] = pdB[mt];
            }
        }
        __syncthreads();
        if (warp_n == 0 && tig == 0) {
#pragma unroll
            for (int mt = 0; mt < 2; ++mt) {
                int lr = warp_m * 32 + mt * 16 + g;
                if (row0 + lr < nrows) {
                    d_as[row0 + lr] = psA[mt] + sd[lr];
                    d_ad[row0 + lr] = pdA[mt] + dd[lr];
                }
                if (row0 + lr + 8 < nrows) {
                    d_as[row0 + lr + 8] = psB[mt] + sd[lr + 8];
                    d_ad[row0 + lr + 8] = pdB[mt] + dd[lr + 8];
                }
            }
        }
    } else if (mode == 1) {
#pragma unroll
        for (int mt = 0; mt < 2; ++mt) {
            int lrA = warp_m * 32 + mt * 16 + g;
            int grA = row0 + lrA;
#pragma unroll
            for (int nt = 0; nt < 8; ++nt) {
                int col = warp_n * 64 + nt * 8 + tig * 2;
                float b0 = bias[col], b1 = bias[col + 1];
                float c0 = fmaxf(acc[mt][nt][0] + b0, 0.f);
                float c1 = fmaxf(acc[mt][nt][1] + b1, 0.f);
                float c2 = fmaxf(acc[mt][nt][2] + b0, 0.f);
                float c3 = fmaxf(acc[mt][nt][3] + b1, 0.f);
                if (grA < nrows) {
                    *(u32*)&Oh[grA * HC + col] = pk_bf16(c0, c1);
                    *(u32*)&Ol[grA * HC + col] = pk_bf16(bf_res(c0), bf_res(c1));
                }
                if (grA + 8 < nrows) {
                    *(u32*)&Oh[(grA + 8) * HC + col] = pk_bf16(c2, c3);
                    *(u32*)&Ol[(grA + 8) * HC + col] = pk_bf16(bf_res(c2), bf_res(c3));
                }
            }
        }
    } else {
        float psA[2] = {0.f, 0.f}, psB[2] = {0.f, 0.f};
#pragma unroll
        for (int mt = 0; mt < 2; ++mt) {
#pragma unroll
            for (int nt = 0; nt < 8; ++nt) {
                int col = warp_n * 64 + nt * 8 + tig * 2;
                float b0 = bias[col], b1 = bias[col + 1];
                float va = v1[col], vb = v1[col + 1];
                psA[mt] += fmaxf(acc[mt][nt][0] + b0, 0.f) * va
                         + fmaxf(acc[mt][nt][1] + b1, 0.f) * vb;
                psB[mt] += fmaxf(acc[mt][nt][2] + b0, 0.f) * va
                         + fmaxf(acc[mt][nt][3] + b1, 0.f) * vb;
            }
        }
#pragma unroll
        for (int mt = 0; mt < 2; ++mt) {
#pragma unroll
            for (int off = 1; off < 4; off <<= 1) {
                psA[mt] += __shfl_xor_sync(0xffffffffu, psA[mt], off);
                psB[mt] += __shfl_xor_sync(0xffffffffu, psB[mt], off);
            }
        }
        float* pp = (float*)(smc + SRED);
        if (warp_n == 1 && tig == 0) {
#pragma unroll
            for (int mt = 0; mt < 2; ++mt) {
                int lr = warp_m * 32 + mt * 16 + g;
                pp[lr] = psA[mt];
                pp[lr + 8] = psB[mt];
            }
        }
        __syncthreads();
        if (warp_n == 0 && tig == 0) {
#pragma unroll
            for (int mt = 0; mt < 2; ++mt) {
                int lr = warp_m * 32 + mt * 16 + g;
                if (row0 + lr < nrows)
                    atomicAdd(&gout[batch[row0 + lr]], psA[mt] + pp[lr]);
                if (row0 + lr + 8 < nrows)
                    atomicAdd(&gout[batch[row0 + lr + 8]], psB[mt] + pp[lr + 8]);
            }
        }
    }
}

// ---------------- fused GAT aggregate: shift-softmax + 8-wide gather groups ----------
__global__ void k_gat(const float* __restrict__ bias, const int* __restrict__ remap,
                      int l, int n) {
    int gw = (blockIdx.x * blockDim.x + threadIdx.x) >> 5;
    int lane = threadIdx.x & 31;
    if (gw >= n) return;
    float ce = d_ce[l];
    int beg = d_rowptr[gw], end = d_rowptr[gw + 1];
    int dmap = remap ? remap[gw] : gw;
    float adn = d_ad[dmap];

    float K = 0.f;
    float ssum = 0.f;
    float4 acc = make_float4(0.f, 0.f, 0.f, 0.f);

    for (int chunk = beg; chunk < end; chunk += 32) {
        int cnt = min(32, end - chunk);
        int sr = 0;
        float w = 0.f, lg = 0.f;
        if (lane < cnt) {
            int2 se = d_csr2[chunk + lane];
            float ea = __int_as_float(se.y);
            sr = remap ? remap[se.x] : se.x;
            float tt = d_as[sr] + adn + ce * ea;
            lg = tt > 0.f ? tt : 0.2f * tt;
        }
        if (chunk == beg) K = __shfl_sync(0xffffffffu, lg, 0);
        if (lane < cnt) w = __expf(lg - K);
        ssum += w;

        for (int c = 0; c < cnt; c += 8) {
            int ss[8]; float ww[8];
#pragma unroll
            for (int q = 0; q < 8; ++q) {
                ss[q] = __shfl_sync(0xffffffffu, sr, c + q);
                ww[q] = __shfl_sync(0xffffffffu, w, c + q);
            }
#pragma unroll
            for (int q = 0; q < 8; ++q) {
                if (ww[q] > 0.f) {
                    float4 v = *(const float4*)&d_xt[ss[q] * HC + lane * 4];
                    acc.x += ww[q] * v.x; acc.y += ww[q] * v.y;
                    acc.z += ww[q] * v.z; acc.w += ww[q] * v.w;
                }
            }
        }
    }

    ssum = warp_sum(ssum);
    float inv = 1.f / ssum;
    float4 b4 = *(const float4*)&bias[lane * 4];
    float4 o;
    o.x = acc.x * inv + b4.x; o.y = acc.y * inv + b4.y;
    o.z = acc.z * inv + b4.z; o.w = acc.w * inv + b4.w;
    float q = o.x * o.x + o.y * o.y + o.z * o.z + o.w * o.w;
    q = warp_sum(q);
    float sc2 = 1.f / fmaxf(sqrtf(q), 1e-12f);
    o.x *= sc2; o.y *= sc2; o.z *= sc2; o.w *= sc2;

    uint2 hw, lw;
    hw.x = pk_bf16(o.x, o.y); hw.y = pk_bf16(o.z, o.w);
    lw.x = pk_bf16(bf_res(o.x), bf_res(o.y));
    lw.y = pk_bf16(bf_res(o.z), bf_res(o.w));
    *(uint2*)&d_hh[gw * HC + lane * 4] = hw;
    *(uint2*)&d_hl[gw * HC + lane * 4] = lw;
}

// ---------------- launcher ----------------
extern "C" void kernel_launch(void* const* d_in, const int* in_sizes, int n_in,
                              void* d_out, int out_size) {
    const int*   x     = (const int*)d_in[0];
    const int*   ei    = (const int*)d_in[1];
    const float* eattr = (const float*)d_in[2];
    const int*   batch = (const int*)d_in[3];
    const float* emb   = (const float*)d_in[4];
    const float* gatW  = (const float*)d_in[5];
    const float* attS  = (const float*)d_in[6];
    const float* attD  = (const float*)d_in[7];
    const float* edgeW = (const float*)d_in[8];
    const float* attE  = (const float*)d_in[9];
    const float* gatB  = (const float*)d_in[10];
    const float* linW  = (const float*)d_in[11];
    const float* linB  = (const float*)d_in[12];
    const float* wpW   = (const float*)d_in[13];
    const float* wpB   = (const float*)d_in[14];
    float* out = (float*)d_out;

    int n = in_sizes[0];
    int e = in_sizes[1] / 2;
    int g = out_size;

    void* p;
    cudaGetSymbolAddress(&p, d_xt);  float* pxt = (float*)p;
    cudaGetSymbolAddress(&p, d_hh);  u16* phh = (u16*)p;
    cudaGetSymbolAddress(&p, d_hl);  u16* phl = (u16*)p;
    cudaGetSymbolAddress(&p, d_gh);  u16* pgh = (u16*)p;
    cudaGetSymbolAddress(&p, d_gl);  u16* pgl = (u16*)p;
    cudaGetSymbolAddress(&p, d_wimg); u16* pw = (u16*)p;

    cudaFuncSetAttribute(k_hmma, cudaFuncAttributeMaxDynamicSharedMemorySize, SMEM_HM);

    int gblocks = (n + 127) / 128;
    int wblocks = (n + 7) / 8;
    int nb = (n + 1023) / 1024;

    // 1..3: setup + count + scan stage 1
    k_setup<<<256, 256>>>(eattr, edgeW, attE, wpB, out, n, e, g);
    k_count<<<(e + 255) / 256, 256>>>(ei, e);
    k_scan1<<<nb, 1024>>>(n);
    // 4: vocab GEMM (independent of CSR) — parallel across 100 blocks
    k_vgemm<<<VV, 128>>>(emb, gatW, attS, attD);
    // 5..7: scan finish + CSR fill
    k_scan2<<<1, 256>>>(nb);
    k_scan3<<<(n + 255) / 256, 256>>>(n);
    k_fill<<<(e + n + 255) / 256, 256>>>(ei, eattr, e, n);
    // 8: weight images
    k_wprep<<<4, 256>>>(gatW, linW);

    // 9: layer-0 GAT aggregate (vocab-factored)
    k_gat<<<wblocks, 256>>>(gatB, x, 0, n);

    // 10..13: layers 1..2
    for (int l = 1; l < NL; ++l) {
        k_hmma<<<gblocks, 256, SMEM_HM>>>(phh, phl, pw + (l - 1) * 32768, (const float*)0,
                                          pxt, attS + l * HC, attD + l * HC,
                                          (const int*)0, (float*)0,
                                          (u16*)0, (u16*)0, n, 0);
        k_gat<<<wblocks, 256>>>(gatB + l * HC, (const int*)0, l, n);
    }

    // 14: dense layer 1
    k_hmma<<<gblocks, 256, SMEM_HM>>>(phh, phl, pw + 2 * 32768, linB,
                                      (float*)0, (const float*)0, (const float*)0,
                                      (const int*)0, (float*)0, pgh, pgl, n, 1);
    // 15: dense layer 2 + fused readout
    k_hmma<<<gblocks, 256, SMEM_HM>>>(pgh, pgl, pw + 3 * 32768, linB + HC,
                                      (float*)0, wpW, (const float*)0,
                                      batch, out, (u16*)0, (u16*)0, n, 2);
}

// round 17
// speedup vs baseline: 1.5379x; 1.1100x over previous
#include <cuda_runtime.h>
#include <cuda_bf16.h>

#define NN 100000
#define EE 400000
#define HC 128
#define NL 3
#define VV 100

typedef unsigned long long u64;
typedef unsigned int u32;
typedef unsigned short u16;

// ---------------- device scratch (static, no allocation) ----------------
__device__ float d_xt[NN * HC];                       // fp32 xt for gathers
__device__ __align__(16) u16 d_hh[NN * HC];           // activation bf16 hi
__device__ __align__(16) u16 d_hl[NN * HC];           // activation bf16 lo
__device__ __align__(16) u16 d_gh[NN * HC];           // dense1 out hi
__device__ __align__(16) u16 d_gl[NN * HC];           // dense1 out lo
__device__ __align__(16) u16 d_wimg[4 * 2 * 16384];   // W^T bf16 hi/lo images
__device__ float d_as[NN];
__device__ float d_ad[NN];
__device__ int   d_deg[NN];
__device__ int   d_incl[NN];
__device__ int   d_rowptr[NN + 1];
__device__ int   d_fillp[NN];
__device__ int2  d_csr2[EE + NN];                     // packed (src, ea bits)
__device__ int   d_bsum[128];
__device__ int   d_boff[128];
__device__ float d_easum[256];
__device__ float d_msum;
__device__ float d_ce[NL];

// ---------------- helpers ----------------
__device__ __forceinline__ float warp_sum(float v) {
#pragma unroll
    for (int o = 16; o; o >>= 1) v += __shfl_xor_sync(0xffffffffu, v, o);
    return v;
}
__device__ __forceinline__ u32 pk_bf16(float lo, float hi) {
    u32 r;
    asm("cvt.rn.bf16x2.f32 %0, %1, %2;" : "=r"(r) : "f"(hi), "f"(lo));
    return r;
}
__device__ __forceinline__ float bf_res(float v) {
    __nv_bfloat16 h = __float2bfloat16(v);
    return v - __bfloat162float(h);
}

// bf16 mma.sync (standard PTX, works on plain sm_103 target)
#define MMA_BF16(c, a, b) \
    asm volatile("mma.sync.aligned.m16n8k16.row.col.f32.bf16.bf16.f32 " \
        "{%0,%1,%2,%3}, {%4,%5,%6,%7}, {%8,%9}, {%0,%1,%2,%3};" \
        : "+f"((c)[0]), "+f"((c)[1]), "+f"((c)[2]), "+f"((c)[3]) \
        : "r"((a)[0]), "r"((a)[1]), "r"((a)[2]), "r"((a)[3]), "r"((b)[0]), "r"((b)[1]))

// ---------------- setup: deg init + ea partial sums + d_ce + out init ----------------
// MUST be launched <<<256, 256>>>.
__global__ void k_setup(const float* __restrict__ ea, const float* __restrict__ eW,
                        const float* __restrict__ aE, const float* __restrict__ wpb,
                        float* __restrict__ out, int n, int e, int g) {
    int t = threadIdx.x;
    int i = blockIdx.x * 256 + t;
    const int stride = 256 * 256;
    for (int j = i; j < n; j += stride) d_deg[j] = 1;        // self loop pre-counted
    for (int j = i; j < g; j += stride) out[j] = wpb[0];
    float s = 0.f;
    for (int j = i; j < e; j += stride) s += ea[j];
    s = warp_sum(s);
    __shared__ float sw[8];
    if ((t & 31) == 0) sw[t >> 5] = s;
    __syncthreads();
    if (t == 0) {
        float tot = 0.f;
#pragma unroll
        for (int k2 = 0; k2 < 8; ++k2) tot += sw[k2];
        d_easum[blockIdx.x] = tot;
    }
    // block 0, warps 0..2: ce[l] = dot(edge_W[l], att_edge[l])
    if (blockIdx.x == 0 && t < NL * 32) {
        int l = t >> 5, lane = t & 31;
        float v = 0.f;
#pragma unroll
        for (int q = 0; q < 4; ++q)
            v += eW[l * HC + lane * 4 + q] * aE[l * HC + lane * 4 + q];
        v = warp_sum(v);
        if (lane == 0) d_ce[l] = v;
    }
}

__global__ void k_count(const int* __restrict__ ei, int e) {
    int i = blockIdx.x * blockDim.x + threadIdx.x;
    if (i < e) atomicAdd(&d_deg[ei[e + i]], 1);
}

__global__ void k_scan1(int n) {
    __shared__ int sh[1024];
    int t = threadIdx.x;
    int i = blockIdx.x * 1024 + t;
    int v = (i < n) ? d_deg[i] : 0;
    sh[t] = v;
    __syncthreads();
#pragma unroll
    for (int off = 1; off < 1024; off <<= 1) {
        int u = (t >= off) ? sh[t - off] : 0;
        __syncthreads();
        sh[t] += u;
        __syncthreads();
    }
    if (i < n) d_incl[i] = sh[t];
    if (t == 1023) d_bsum[blockIdx.x] = sh[1023];
}

// 256 threads, 1 block: block-offset scan + finalize d_msum
__global__ void k_scan2(int nb) {
    __shared__ int sh[256];
    __shared__ float fm[8];
    int t = threadIdx.x;
    float ms = d_easum[t];
    ms = warp_sum(ms);
    if ((t & 31) == 0) fm[t >> 5] = ms;
    int v = (t < nb) ? d_bsum[t] : 0;
    sh[t] = v;
    __syncthreads();
    if (t == 0) {
        float tot = 0.f;
#pragma unroll
        for (int k2 = 0; k2 < 8; ++k2) tot += fm[k2];
        d_msum = tot;
    }
#pragma unroll
    for (int off = 1; off < 256; off <<= 1) {
        int u = (t >= off) ? sh[t - off] : 0;
        __syncthreads();
        sh[t] += u;
        __syncthreads();
    }
    if (t < nb) d_boff[t] = sh[t] - v;
}

__global__ void k_scan3(int n) {
    int i = blockIdx.x * blockDim.x + threadIdx.x;
    if (i >= n) return;
    int v = d_incl[i] + d_boff[i >> 10];
    d_rowptr[i + 1] = v;
    if (i + 1 < n) d_fillp[i + 1] = v;
    if (i == 0) { d_rowptr[0] = 0; d_fillp[0] = 0; }
}

__global__ void k_fill(const int* __restrict__ ei, const float* __restrict__ eattr,
                       int e, int n) {
    int i = blockIdx.x * blockDim.x + threadIdx.x;
    if (i >= e + n) return;
    int s, d;
    float ea;
    if (i < e) { s = ei[i]; d = ei[e + i]; ea = eattr[i]; }
    else { s = d = i - e; ea = d_msum * (1.0f / (float)e); }
    int p = atomicAdd(&d_fillp[d], 1);
    d_csr2[p] = make_int2(s, __float_as_int(ea));
}

// weight prep: W[k][n] (fp32) -> W^T[n][k] bf16 hi and lo, dense row-major
__global__ void k_wprep(const float* __restrict__ gatW, const float* __restrict__ linW) {
    const float* W = (blockIdx.x < 2) ? gatW + (blockIdx.x + 1) * HC * HC
                                      : linW + (blockIdx.x - 2) * HC * HC;
    u16* Gh = d_wimg + blockIdx.x * 32768;
    u16* Gl = Gh + 16384;
    for (int idx = threadIdx.x; idx < 16384; idx += 256) {
        int k = idx >> 7, nn = idx & 127;
        float v = W[idx];
        __nv_bfloat16 h = __float2bfloat16(v);
        float rv = v - __bfloat162float(h);
        __nv_bfloat16 lo = __float2bfloat16(rv);
        Gh[nn * HC + k] = __bfloat16_as_ushort(h);
        Gl[nn * HC + k] = __bfloat16_as_ushort(lo);
    }
}

// ---------------- vocab GEMM: one block per emb row (100 blocks, parallel) --------
__global__ void __launch_bounds__(128, 8)
k_vgemm(const float* __restrict__ emb, const float* __restrict__ W,
        const float* __restrict__ v1, const float* __restrict__ v2) {
    int r = blockIdx.x, c = threadIdx.x;
    __shared__ float row[HC];
    __shared__ float s1[4], s2[4];
    row[c] = emb[r * HC + c];
    __syncthreads();
    float acc = 0.f;
#pragma unroll
    for (int k = 0; k < HC; ++k)
        acc = fmaf(row[k], W[k * HC + c], acc);
    d_xt[r * HC + c] = acc;
    float ps = acc * v1[c], pd = acc * v2[c];
    ps = warp_sum(ps); pd = warp_sum(pd);
    if ((c & 31) == 0) { s1[c >> 5] = ps; s2[c >> 5] = pd; }
    __syncthreads();
    if (c == 0) d_as[r] = s1[0] + s1[1] + s1[2] + s1[3];
    if (c == 1) d_ad[r] = s2[0] + s2[1] + s2[2] + s2[3];
}

// ---------------- HMMA GEMM (mma.sync bf16, bf16x3 split) ----------------
// Validated R10 config: A and W both staged in SMEM at 272B row stride.
#define ROWB 272
#define SA_H 0
#define SA_L 34816
#define SW_H 69632
#define SW_L 104448
#define SRED 139264
#define SMEM_HM (139264 + 1024)

__global__ void __launch_bounds__(256, 1)
k_hmma(const u16* __restrict__ Ah, const u16* __restrict__ Al,
       const u16* __restrict__ Wimg, const float* __restrict__ bias,
       float* __restrict__ C, const float* __restrict__ v1, const float* __restrict__ v2,
       const int* __restrict__ batch, float* __restrict__ gout,
       u16* __restrict__ Oh, u16* __restrict__ Ol, int nrows, int mode) {
    extern __shared__ char smc[];
    int t = threadIdx.x;
    int wid = t >> 5, lane = t & 31;
    int row0 = blockIdx.x * 128;
    int g = lane >> 2, tig = lane & 3;
    int warp_m = wid & 3, warp_n = wid >> 2;

    const uint4* A4h = (const uint4*)Ah;
    const uint4* A4l = (const uint4*)Al;
#pragma unroll
    for (int i = 0; i < 8; ++i) {
        int idx = t + i * 256;
        int r = idx >> 4, c8 = idx & 15;
        uint4 vh = make_uint4(0, 0, 0, 0), vl = vh;
        if (row0 + r < nrows) {
            vh = A4h[(row0 + r) * 16 + c8];
            vl = A4l[(row0 + r) * 16 + c8];
        }
        *(uint4*)(smc + SA_H + r * ROWB + c8 * 16) = vh;
        *(uint4*)(smc + SA_L + r * ROWB + c8 * 16) = vl;
    }
    const uint4* Wh4 = (const uint4*)Wimg;
    const uint4* Wl4 = (const uint4*)(Wimg + 16384);
#pragma unroll
    for (int i = 0; i < 8; ++i) {
        int idx = t + i * 256;
        int r = idx >> 4, c8 = idx & 15;
        *(uint4*)(smc + SW_H + r * ROWB + c8 * 16) = Wh4[idx];
        *(uint4*)(smc + SW_L + r * ROWB + c8 * 16) = Wl4[idx];
    }
    __syncthreads();

    float acc[2][8][4];
#pragma unroll
    for (int mt = 0; mt < 2; ++mt)
#pragma unroll
        for (int nt = 0; nt < 8; ++nt)
#pragma unroll
            for (int j = 0; j < 4; ++j) acc[mt][nt][j] = 0.f;

#pragma unroll
    for (int ks = 0; ks < 8; ++ks) {
        u32 ah[2][4], al[2][4];
#pragma unroll
        for (int mt = 0; mt < 2; ++mt) {
            int rb = (warp_m * 32 + mt * 16 + g) * ROWB + ks * 32 + tig * 4;
            int rb8 = rb + 8 * ROWB;
            ah[mt][0] = *(const u32*)(smc + SA_H + rb);
            ah[mt][1] = *(const u32*)(smc + SA_H + rb8);
            ah[mt][2] = *(const u32*)(smc + SA_H + rb + 16);
            ah[mt][3] = *(const u32*)(smc + SA_H + rb8 + 16);
            al[mt][0] = *(const u32*)(smc + SA_L + rb);
            al[mt][1] = *(const u32*)(smc + SA_L + rb8);
            al[mt][2] = *(const u32*)(smc + SA_L + rb + 16);
            al[mt][3] = *(const u32*)(smc + SA_L + rb8 + 16);
        }
#pragma unroll
        for (int nt = 0; nt < 8; ++nt) {
            int nb = (warp_n * 64 + nt * 8 + g) * ROWB + ks * 32 + tig * 4;
            u32 bh[2], bl[2];
            bh[0] = *(const u32*)(smc + SW_H + nb);
            bh[1] = *(const u32*)(smc + SW_H + nb + 16);
            bl[0] = *(const u32*)(smc + SW_L + nb);
            bl[1] = *(const u32*)(smc + SW_L + nb + 16);
#pragma unroll
            for (int mt = 0; mt < 2; ++mt) {
                MMA_BF16(acc[mt][nt], ah[mt], bh);
                MMA_BF16(acc[mt][nt], ah[mt], bl);
                MMA_BF16(acc[mt][nt], al[mt], bh);
            }
        }
    }
    __syncthreads();

    if (mode == 0) {
        float psA[2] = {0.f, 0.f}, psB[2] = {0.f, 0.f};
        float pdA[2] = {0.f, 0.f}, pdB[2] = {0.f, 0.f};
#pragma unroll
        for (int mt = 0; mt < 2; ++mt) {
            int lrA = warp_m * 32 + mt * 16 + g;
#pragma unroll
            for (int nt = 0; nt < 8; ++nt) {
                int col = warp_n * 64 + nt * 8 + tig * 2;
                float c0 = acc[mt][nt][0], c1 = acc[mt][nt][1];
                float c2 = acc[mt][nt][2], c3 = acc[mt][nt][3];
                float va = v1[col], vb = v1[col + 1];
                float wa = v2[col], wb = v2[col + 1];
                psA[mt] += c0 * va + c1 * vb;  pdA[mt] += c0 * wa + c1 * wb;
                psB[mt] += c2 * va + c3 * vb;  pdB[mt] += c2 * wa + c3 * wb;
                int grA = row0 + lrA;
                if (grA < nrows)
                    *(float2*)&C[grA * HC + col] = make_float2(c0, c1);
                if (grA + 8 < nrows)
                    *(float2*)&C[(grA + 8) * HC + col] = make_float2(c2, c3);
            }
        }
#pragma unroll
        for (int mt = 0; mt < 2; ++mt) {
#pragma unroll
            for (int off = 1; off < 4; off <<= 1) {
                psA[mt] += __shfl_xor_sync(0xffffffffu, psA[mt], off);
                psB[mt] += __shfl_xor_sync(0xffffffffu, psB[mt], off);
                pdA[mt] += __shfl_xor_sync(0xffffffffu, pdA[mt], off);
                pdB[mt] += __shfl_xor_sync(0xffffffffu, pdB[mt], off);
            }
        }
        float* sd = (float*)(smc + SRED);
        float* dd = sd + 128;
        if (warp_n == 1 && tig == 0) {
#pragma unroll
            for (int mt = 0; mt < 2; ++mt) {
                int lr = warp_m * 32 + mt * 16 + g;
                sd[lr] = psA[mt]; dd[lr] = pdA[mt];
                sd[lr + 8] = psB[mt]; dd[lr + 8] = pdB[mt];
            }
        }
        __syncthreads();
        if (warp_n == 0 && tig == 0) {
#pragma unroll
            for (int mt = 0; mt < 2; ++mt) {
                int lr = warp_m * 32 + mt * 16 + g;
                if (row0 + lr < nrows) {
                    d_as[row0 + lr] = psA[mt] + sd[lr];
                    d_ad[row0 + lr] = pdA[mt] + dd[lr];
                }
                if (row0 + lr + 8 < nrows) {
                    d_as[row0 + lr + 8] = psB[mt] + sd[lr + 8];
                    d_ad[row0 + lr + 8] = pdB[mt] + dd[lr + 8];
                }
            }
        }
    } else if (mode == 1) {
#pragma unroll
        for (int mt = 0; mt < 2; ++mt) {
            int lrA = warp_m * 32 + mt * 16 + g;
            int grA = row0 + lrA;
#pragma unroll
            for (int nt = 0; nt < 8; ++nt) {
                int col = warp_n * 64 + nt * 8 + tig * 2;
                float b0 = bias[col], b1 = bias[col + 1];
                float c0 = fmaxf(acc[mt][nt][0] + b0, 0.f);
                float c1 = fmaxf(acc[mt][nt][1] + b1, 0.f);
                float c2 = fmaxf(acc[mt][nt][2] + b0, 0.f);
                float c3 = fmaxf(acc[mt][nt][3] + b1, 0.f);
                if (grA < nrows) {
                    *(u32*)&Oh[grA * HC + col] = pk_bf16(c0, c1);
                    *(u32*)&Ol[grA * HC + col] = pk_bf16(bf_res(c0), bf_res(c1));
                }
                if (grA + 8 < nrows) {
                    *(u32*)&Oh[(grA + 8) * HC + col] = pk_bf16(c2, c3);
                    *(u32*)&Ol[(grA + 8) * HC + col] = pk_bf16(bf_res(c2), bf_res(c3));
                }
            }
        }
    } else {
        float psA[2] = {0.f, 0.f}, psB[2] = {0.f, 0.f};
#pragma unroll
        for (int mt = 0; mt < 2; ++mt) {
#pragma unroll
            for (int nt = 0; nt < 8; ++nt) {
                int col = warp_n * 64 + nt * 8 + tig * 2;
                float b0 = bias[col], b1 = bias[col + 1];
                float va = v1[col], vb = v1[col + 1];
                psA[mt] += fmaxf(acc[mt][nt][0] + b0, 0.f) * va
                         + fmaxf(acc[mt][nt][1] + b1, 0.f) * vb;
                psB[mt] += fmaxf(acc[mt][nt][2] + b0, 0.f) * va
                         + fmaxf(acc[mt][nt][3] + b1, 0.f) * vb;
            }
        }
#pragma unroll
        for (int mt = 0; mt < 2; ++mt) {
#pragma unroll
            for (int off = 1; off < 4; off <<= 1) {
                psA[mt] += __shfl_xor_sync(0xffffffffu, psA[mt], off);
                psB[mt] += __shfl_xor_sync(0xffffffffu, psB[mt], off);
            }
        }
        float* pp = (float*)(smc + SRED);
        if (warp_n == 1 && tig == 0) {
#pragma unroll
            for (int mt = 0; mt < 2; ++mt) {
                int lr = warp_m * 32 + mt * 16 + g;
                pp[lr] = psA[mt];
                pp[lr + 8] = psB[mt];
            }
        }
        __syncthreads();
        if (warp_n == 0 && tig == 0) {
#pragma unroll
            for (int mt = 0; mt < 2; ++mt) {
                int lr = warp_m * 32 + mt * 16 + g;
                if (row0 + lr < nrows)
                    atomicAdd(&gout[batch[row0 + lr]], psA[mt] + pp[lr]);
                if (row0 + lr + 8 < nrows)
                    atomicAdd(&gout[batch[row0 + lr + 8]], psB[mt] + pp[lr + 8]);
            }
        }
    }
}

// ---------------- fused GAT aggregate: shift-softmax + R10 4-wide gather ----------
__global__ void k_gat(const float* __restrict__ bias, const int* __restrict__ remap,
                      int l, int n) {
    int gw = (blockIdx.x * blockDim.x + threadIdx.x) >> 5;
    int lane = threadIdx.x & 31;
    if (gw >= n) return;
    float ce = d_ce[l];
    int beg = d_rowptr[gw], end = d_rowptr[gw + 1];
    int dmap = remap ? remap[gw] : gw;
    float adn = d_ad[dmap];

    float K = 0.f;
    float ssum = 0.f;
    float4 acc = make_float4(0.f, 0.f, 0.f, 0.f);

    for (int chunk = beg; chunk < end; chunk += 32) {
        int cnt = min(32, end - chunk);
        int sr = 0;
        float w = 0.f, lg = 0.f;
        if (lane < cnt) {
            int2 se = d_csr2[chunk + lane];
            float ea = __int_as_float(se.y);
            sr = remap ? remap[se.x] : se.x;
            float tt = d_as[sr] + adn + ce * ea;
            lg = tt > 0.f ? tt : 0.2f * tt;
        }
        if (chunk == beg) K = __shfl_sync(0xffffffffu, lg, 0);
        if (lane < cnt) w = __expf(lg - K);
        ssum += w;

        for (int c = 0; c < cnt; c += 4) {
            int s0 = __shfl_sync(0xffffffffu, sr, c);
            int s1 = __shfl_sync(0xffffffffu, sr, c + 1);
            int s2 = __shfl_sync(0xffffffffu, sr, c + 2);
            int s3 = __shfl_sync(0xffffffffu, sr, c + 3);
            float w0 = __shfl_sync(0xffffffffu, w, c);
            float w1 = __shfl_sync(0xffffffffu, w, c + 1);
            float w2 = __shfl_sync(0xffffffffu, w, c + 2);
            float w3 = __shfl_sync(0xffffffffu, w, c + 3);
            if (w0 > 0.f) {
                float4 v = *(const float4*)&d_xt[s0 * HC + lane * 4];
                acc.x += w0 * v.x; acc.y += w0 * v.y;
                acc.z += w0 * v.z; acc.w += w0 * v.w;
            }
            if (w1 > 0.f) {
                float4 v = *(const float4*)&d_xt[s1 * HC + lane * 4];
                acc.x += w1 * v.x; acc.y += w1 * v.y;
                acc.z += w1 * v.z; acc.w += w1 * v.w;
            }
            if (w2 > 0.f) {
                float4 v = *(const float4*)&d_xt[s2 * HC + lane * 4];
                acc.x += w2 * v.x; acc.y += w2 * v.y;
                acc.z += w2 * v.z; acc.w += w2 * v.w;
            }
            if (w3 > 0.f) {
                float4 v = *(const float4*)&d_xt[s3 * HC + lane * 4];
                acc.x += w3 * v.x; acc.y += w3 * v.y;
                acc.z += w3 * v.z; acc.w += w3 * v.w;
            }
        }
    }

    ssum = warp_sum(ssum);
    float inv = 1.f / ssum;
    float4 b4 = *(const float4*)&bias[lane * 4];
    float4 o;
    o.x = acc.x * inv + b4.x; o.y = acc.y * inv + b4.y;
    o.z = acc.z * inv + b4.z; o.w = acc.w * inv + b4.w;
    float q = o.x * o.x + o.y * o.y + o.z * o.z + o.w * o.w;
    q = warp_sum(q);
    float sc2 = 1.f / fmaxf(sqrtf(q), 1e-12f);
    o.x *= sc2; o.y *= sc2; o.z *= sc2; o.w *= sc2;

    uint2 hw, lw;
    hw.x = pk_bf16(o.x, o.y); hw.y = pk_bf16(o.z, o.w);
    lw.x = pk_bf16(bf_res(o.x), bf_res(o.y));
    lw.y = pk_bf16(bf_res(o.z), bf_res(o.w));
    *(uint2*)&d_hh[gw * HC + lane * 4] = hw;
    *(uint2*)&d_hl[gw * HC + lane * 4] = lw;
}

// ---------------- launcher ----------------
extern "C" void kernel_launch(void* const* d_in, const int* in_sizes, int n_in,
                              void* d_out, int out_size) {
    const int*   x     = (const int*)d_in[0];
    const int*   ei    = (const int*)d_in[1];
    const float* eattr = (const float*)d_in[2];
    const int*   batch = (const int*)d_in[3];
    const float* emb   = (const float*)d_in[4];
    const float* gatW  = (const float*)d_in[5];
    const float* attS  = (const float*)d_in[6];
    const float* attD  = (const float*)d_in[7];
    const float* edgeW = (const float*)d_in[8];
    const float* attE  = (const float*)d_in[9];
    const float* gatB  = (const float*)d_in[10];
    const float* linW  = (const float*)d_in[11];
    const float* linB  = (const float*)d_in[12];
    const float* wpW   = (const float*)d_in[13];
    const float* wpB   = (const float*)d_in[14];
    float* out = (float*)d_out;

    int n = in_sizes[0];
    int e = in_sizes[1] / 2;
    int g = out_size;

    void* p;
    cudaGetSymbolAddress(&p, d_xt);  float* pxt = (float*)p;
    cudaGetSymbolAddress(&p, d_hh);  u16* phh = (u16*)p;
    cudaGetSymbolAddress(&p, d_hl);  u16* phl = (u16*)p;
    cudaGetSymbolAddress(&p, d_gh);  u16* pgh = (u16*)p;
    cudaGetSymbolAddress(&p, d_gl);  u16* pgl = (u16*)p;
    cudaGetSymbolAddress(&p, d_wimg); u16* pw = (u16*)p;

    cudaFuncSetAttribute(k_hmma, cudaFuncAttributeMaxDynamicSharedMemorySize, SMEM_HM);

    int gblocks = (n + 127) / 128;
    int wblocks = (n + 7) / 8;
    int nb = (n + 1023) / 1024;

    // 1..3: setup + count + scan stage 1
    k_setup<<<256, 256>>>(eattr, edgeW, attE, wpB, out, n, e, g);
    k_count<<<(e + 255) / 256, 256>>>(ei, e);
    k_scan1<<<nb, 1024>>>(n);
    // 4: vocab GEMM (independent of CSR) — parallel across 100 blocks
    k_vgemm<<<VV, 128>>>(emb, gatW, attS, attD);
    // 5..7: scan finish + CSR fill
    k_scan2<<<1, 256>>>(nb);
    k_scan3<<<(n + 255) / 256, 256>>>(n);
    k_fill<<<(e + n + 255) / 256, 256>>>(ei, eattr, e, n);
    // 8: weight images
    k_wprep<<<4, 256>>>(gatW, linW);

    // 9: layer-0 GAT aggregate (vocab-factored)
    k_gat<<<wblocks, 256>>>(gatB, x, 0, n);

    // 10..13: layers 1..2
    for (int l = 1; l < NL; ++l) {
        k_hmma<<<gblocks, 256, SMEM_HM>>>(phh, phl, pw + (l - 1) * 32768, (const float*)0,
                                          pxt, attS + l * HC, attD + l * HC,
                                          (const int*)0, (float*)0,
                                          (u16*)0, (u16*)0, n, 0);
        k_gat<<<wblocks, 256>>>(gatB + l * HC, (const int*)0, l, n);
    }

    // 14: dense layer 1
    k_hmma<<<gblocks, 256, SMEM_HM>>>(phh, phl, pw + 2 * 32768, linB,
                                      (float*)0, (const float*)0, (const float*)0,
                                      (const int*)0, (float*)0, pgh, pgl, n, 1);
    // 15: dense layer 2 + fused readout
    k_hmma<<<gblocks, 256, SMEM_HM>>>(pgh, pgl, pw + 3 * 32768, linB + HC,
                                      (float*)0, wpW, (const float*)0,
                                      batch, out, (u16*)0, (u16*)0, n, 2);
}